// round 7
// baseline (speedup 1.0000x reference)
#include <cuda_runtime.h>

// ---------------------------------------------------------------------------
// VQ (vector-quantization) forward:
//   f = x @ W^T + b                       [N, 256]
//   idx = argmin_k ||f - e_k||^2          [N]     (K = 1024 codes)
//   quantized_st = x + (e[idx] - x)       [N, 256]
//   loss = 0.25 * mean((e[idx] - x)^2)
//   perplexity = exp(-sum p log(p+1e-10)), p = histogram(idx)/N
//   encodings = one_hot(idx, K) f32       [N, K]
//
// Output layout (flattened tuple): [loss(1) | quantized(N*256) | perp(1) | enc(N*K)]
// ---------------------------------------------------------------------------

#define NTOK   (64 * 2048)         // 131072
#define DDIM   256
#define KCODE  1024
#define QOFF   1
#define PERPOFF (1 + NTOK * DDIM)  // 33554433
#define ENCOFF  (PERPOFF + 1)      // 33554434

// scratch (static device globals: no runtime allocation)
__device__ float  g_enorm[KCODE];
__device__ int    g_idx[NTOK];
__device__ int    g_cnt[KCODE];
__device__ double g_loss;

typedef unsigned long long u64;

// ---- packed f32x2 helpers (Blackwell FFMA2: 2x fp32 FMA throughput) -------
__device__ __forceinline__ u64 pk2(float lo, float hi) {
    u64 r; asm("mov.b64 %0, {%1,%2};" : "=l"(r) : "f"(lo), "f"(hi)); return r;
}
__device__ __forceinline__ u64 ffma2(u64 a, u64 b, u64 c) {
    u64 d; asm("fma.rn.f32x2 %0, %1, %2, %3;" : "=l"(d) : "l"(a), "l"(b), "l"(c)); return d;
}
__device__ __forceinline__ float2 upk2(u64 v) {
    float lo, hi; asm("mov.b64 {%0,%1}, %2;" : "=f"(lo), "=f"(hi) : "l"(v));
    return make_float2(lo, hi);
}

// ---- shared-memory layout for the fused kernel ----------------------------
#define SPITCH       132                       // padded pitch (floats) to dodge bank conflicts
#define FS_FLOATS    (256 * SPITCH)            // resident f tile, stored [k][m]
#define STAGE_FLOATS (16 * SPITCH)             // one 128x16 stage tile, stored [k][row]
#define SMEM_FLOATS  (FS_FLOATS + 2 * STAGE_FLOATS + 128)
#define SMEM_BYTES   (SMEM_FLOATS * 4)

// Load a 128-row x 16-col tile (row stride DDIM) into registers: 2x float4/thread.
__device__ __forceinline__ void ldg_tile(const float* __restrict__ src, int tid,
                                         float4& v0, float4& v1) {
    int r0 = tid >> 2, c0 = (tid & 3) << 2;
    v0 = *reinterpret_cast<const float4*>(src + r0 * DDIM + c0);
    int id1 = tid + 256;
    int r1 = id1 >> 2, c1 = (id1 & 3) << 2;
    v1 = *reinterpret_cast<const float4*>(src + r1 * DDIM + c1);
}
// Store those registers transposed into smem stage tile S[k][row] (pitch SPITCH).
__device__ __forceinline__ void sts_tile(float* S, int tid,
                                         const float4& v0, const float4& v1) {
    int r0 = tid >> 2, c0 = (tid & 3) << 2;
    S[(c0 + 0) * SPITCH + r0] = v0.x;
    S[(c0 + 1) * SPITCH + r0] = v0.y;
    S[(c0 + 2) * SPITCH + r0] = v0.z;
    S[(c0 + 3) * SPITCH + r0] = v0.w;
    int id1 = tid + 256;
    int r1 = id1 >> 2, c1 = (id1 & 3) << 2;
    S[(c1 + 0) * SPITCH + r1] = v1.x;
    S[(c1 + 1) * SPITCH + r1] = v1.y;
    S[(c1 + 2) * SPITCH + r1] = v1.z;
    S[(c1 + 3) * SPITCH + r1] = v1.w;
}

// One k-step of the 8x8 micro-tile (packed over column pairs): 32 FFMA2 = 64 FMA.
__device__ __forceinline__ void mm_step(const float* __restrict__ a_row,
                                        const float* __restrict__ b_row,
                                        int ty8, int tx8, u64* acc) {
    float4 aA = *reinterpret_cast<const float4*>(a_row + ty8);
    float4 aB = *reinterpret_cast<const float4*>(a_row + ty8 + 4);
    float4 bA = *reinterpret_cast<const float4*>(b_row + tx8);
    float4 bB = *reinterpret_cast<const float4*>(b_row + tx8 + 4);
    u64 b2[4];
    b2[0] = pk2(bA.x, bA.y); b2[1] = pk2(bA.z, bA.w);
    b2[2] = pk2(bB.x, bB.y); b2[3] = pk2(bB.z, bB.w);
    float av[8] = {aA.x, aA.y, aA.z, aA.w, aB.x, aB.y, aB.z, aB.w};
#pragma unroll
    for (int i = 0; i < 8; i++) {
        u64 aa = pk2(av[i], av[i]);
#pragma unroll
        for (int j = 0; j < 4; j++) acc[i * 4 + j] = ffma2(aa, b2[j], acc[i * 4 + j]);
    }
}

// ---------------------------------------------------------------------------
// Fused kernel: per CTA of 128 tokens:
//   phase 1: f tile = x @ W^T + b  (resident in smem, transposed [k][m])
//   phase 2: distances vs all 1024 codes, argmin with first-index tie-break,
//            histogram atomics.
// ---------------------------------------------------------------------------
__global__ void __launch_bounds__(256, 1)
vq_main(const float* __restrict__ x, const float* __restrict__ W,
        const float* __restrict__ bias, const float* __restrict__ E) {
    extern __shared__ float sm[];
    float* f_s  = sm;                          // [256][SPITCH]
    float* As   = sm + FS_FLOATS;              // [16][SPITCH]
    float* Bs   = As + STAGE_FLOATS;           // [16][SPITCH]
    float* f2_s = Bs + STAGE_FLOATS;           // [128]

    const int tid = threadIdx.x;
    const int tx = tid & 15, ty = tid >> 4;
    const int tx8 = tx * 8, ty8 = ty * 8;
    const int row0 = blockIdx.x * 128;
    const float* xbase = x + (size_t)row0 * DDIM;

    // ---------------- phase 1: pre-linear ----------------
#pragma unroll 1
    for (int jt = 0; jt < 2; jt++) {
        u64 acc[32];
#pragma unroll
        for (int i = 0; i < 32; i++) acc[i] = 0ull;
        const float* wsrc = W + (size_t)jt * 128 * DDIM;
        float4 a0, a1, b0, b1;
        ldg_tile(xbase, tid, a0, a1);
        ldg_tile(wsrc, tid, b0, b1);
#pragma unroll 1
        for (int s = 0; s < 16; s++) {
            __syncthreads();
            sts_tile(As, tid, a0, a1);
            sts_tile(Bs, tid, b0, b1);
            if (s < 15) {
                ldg_tile(xbase + (s + 1) * 16, tid, a0, a1);
                ldg_tile(wsrc + (s + 1) * 16, tid, b0, b1);
            }
            __syncthreads();
#pragma unroll
            for (int kk = 0; kk < 16; kk++)
                mm_step(As + kk * SPITCH, Bs + kk * SPITCH, ty8, tx8, acc);
        }
        // epilogue: f_s[col][row] = acc + bias
        float4 bb0 = *reinterpret_cast<const float4*>(bias + jt * 128 + tx8);
        float4 bb1 = *reinterpret_cast<const float4*>(bias + jt * 128 + tx8 + 4);
        float bv[8] = {bb0.x, bb0.y, bb0.z, bb0.w, bb1.x, bb1.y, bb1.z, bb1.w};
#pragma unroll
        for (int i = 0; i < 8; i++) {
            int row = ty8 + i;
#pragma unroll
            for (int jp = 0; jp < 4; jp++) {
                float2 v = upk2(acc[i * 4 + jp]);
                int c = jt * 128 + tx8 + jp * 2;
                f_s[(c + 0) * SPITCH + row] = v.x + bv[jp * 2 + 0];
                f_s[(c + 1) * SPITCH + row] = v.y + bv[jp * 2 + 1];
            }
        }
    }
    __syncthreads();

    // per-token ||f||^2
    if (tid < 128) {
        float s = 0.0f;
        for (int k = 0; k < 256; k++) {
            float v = f_s[k * SPITCH + tid];
            s = __fmaf_rn(v, v, s);
        }
        f2_s[tid] = s;
    }
    __syncthreads();

    // ---------------- phase 2: distances + argmin ----------------
    float bestv[8];
    int besti[8];
#pragma unroll
    for (int i = 0; i < 8; i++) { bestv[i] = 3.4e38f; besti[i] = 0; }

#pragma unroll 1
    for (int nt = 0; nt < 8; nt++) {
        u64 acc[32];
#pragma unroll
        for (int i = 0; i < 32; i++) acc[i] = 0ull;
        const float* esrc = E + (size_t)nt * 128 * DDIM;
        float4 b0, b1;
        ldg_tile(esrc, tid, b0, b1);
#pragma unroll 1
        for (int s = 0; s < 16; s++) {
            __syncthreads();
            sts_tile(Bs, tid, b0, b1);
            if (s < 15) ldg_tile(esrc + (s + 1) * 16, tid, b0, b1);
            __syncthreads();
#pragma unroll
            for (int kk = 0; kk < 16; kk++)
                mm_step(f_s + (s * 16 + kk) * SPITCH, Bs + kk * SPITCH, ty8, tx8, acc);
        }
        // epilogue: d = (||f||^2 + ||e||^2) - 2*dot  (match reference rounding)
        float4 e0 = *reinterpret_cast<const float4*>(g_enorm + nt * 128 + tx8);
        float4 e1 = *reinterpret_cast<const float4*>(g_enorm + nt * 128 + tx8 + 4);
        float en[8] = {e0.x, e0.y, e0.z, e0.w, e1.x, e1.y, e1.z, e1.w};
#pragma unroll
        for (int i = 0; i < 8; i++) {
            float f2 = f2_s[ty8 + i];
#pragma unroll
            for (int jp = 0; jp < 4; jp++) {
                float2 v = upk2(acc[i * 4 + jp]);
                int c = nt * 128 + tx8 + jp * 2;
                float d0 = __fsub_rn(__fadd_rn(f2, en[jp * 2 + 0]), __fmul_rn(2.0f, v.x));
                float d1 = __fsub_rn(__fadd_rn(f2, en[jp * 2 + 1]), __fmul_rn(2.0f, v.y));
                if (d0 < bestv[i]) { bestv[i] = d0; besti[i] = c; }
                if (d1 < bestv[i]) { bestv[i] = d1; besti[i] = c + 1; }
            }
        }
    }

    // reduce across the 16 tx threads holding the same 8 tokens (within warp half)
#pragma unroll
    for (int i = 0; i < 8; i++) {
        float v = bestv[i];
        int ix = besti[i];
#pragma unroll
        for (int o = 8; o; o >>= 1) {
            float ov = __shfl_xor_sync(0xffffffffu, v, o);
            int   oi = __shfl_xor_sync(0xffffffffu, ix, o);
            if (ov < v || (ov == v && oi < ix)) { v = ov; ix = oi; }
        }
        if (tx == 0) {
            int token = row0 + ty8 + i;
            g_idx[token] = ix;
            atomicAdd(&g_cnt[ix], 1);
        }
    }
}

// ---------------------------------------------------------------------------
// Small kernels
// ---------------------------------------------------------------------------
__global__ void init_k() {
    int t = threadIdx.x;
    if (t < KCODE) g_cnt[t] = 0;
    if (t == 0) g_loss = 0.0;
}

__global__ void enorm_k(const float* __restrict__ E) {
    int k = blockIdx.x, lane = threadIdx.x;
    const float4* e4 = reinterpret_cast<const float4*>(E + (size_t)k * DDIM);
    float4 a = e4[lane * 2], b = e4[lane * 2 + 1];
    float s = a.x * a.x + a.y * a.y + a.z * a.z + a.w * a.w
            + b.x * b.x + b.y * b.y + b.z * b.z + b.w * b.w;
#pragma unroll
    for (int o = 16; o; o >>= 1) s += __shfl_xor_sync(0xffffffffu, s, o);
    if (lane == 0) g_enorm[k] = s;
}

__global__ void enc_zero(float* __restrict__ out) {
    float2* p = reinterpret_cast<float2*>(out + ENCOFF);  // even offset -> 8B aligned
    long long n = (long long)NTOK * KCODE / 2;
    long long i = (long long)blockIdx.x * blockDim.x + threadIdx.x;
    long long stride = (long long)gridDim.x * blockDim.x;
    float2 z = make_float2(0.0f, 0.0f);
    for (; i < n; i += stride) p[i] = z;
}

__global__ void enc_ones(float* __restrict__ out) {
    int n = blockIdx.x * blockDim.x + threadIdx.x;
    if (n < NTOK) out[(long long)ENCOFF + (long long)n * KCODE + g_idx[n]] = 1.0f;
}

__global__ void quant_loss(float* __restrict__ out, const float* __restrict__ x,
                           const float* __restrict__ E) {
    int warp = (blockIdx.x * blockDim.x + threadIdx.x) >> 5;
    int lane = threadIdx.x & 31;
    if (warp >= NTOK) return;
    int c = g_idx[warp];
    const float4* e4 = reinterpret_cast<const float4*>(E + (size_t)c * DDIM);
    const float4* x4 = reinterpret_cast<const float4*>(x + (size_t)warp * DDIM);
    float4 e0 = e4[lane * 2], e1 = e4[lane * 2 + 1];
    float4 v0 = x4[lane * 2], v1 = x4[lane * 2 + 1];
    float* q = out + QOFF + (size_t)warp * DDIM + lane * 8;
    float s = 0.0f, d;
    d = __fsub_rn(e0.x, v0.x); q[0] = __fadd_rn(v0.x, d); s = __fmaf_rn(d, d, s);
    d = __fsub_rn(e0.y, v0.y); q[1] = __fadd_rn(v0.y, d); s = __fmaf_rn(d, d, s);
    d = __fsub_rn(e0.z, v0.z); q[2] = __fadd_rn(v0.z, d); s = __fmaf_rn(d, d, s);
    d = __fsub_rn(e0.w, v0.w); q[3] = __fadd_rn(v0.w, d); s = __fmaf_rn(d, d, s);
    d = __fsub_rn(e1.x, v1.x); q[4] = __fadd_rn(v1.x, d); s = __fmaf_rn(d, d, s);
    d = __fsub_rn(e1.y, v1.y); q[5] = __fadd_rn(v1.y, d); s = __fmaf_rn(d, d, s);
    d = __fsub_rn(e1.z, v1.z); q[6] = __fadd_rn(v1.z, d); s = __fmaf_rn(d, d, s);
    d = __fsub_rn(e1.w, v1.w); q[7] = __fadd_rn(v1.w, d); s = __fmaf_rn(d, d, s);
#pragma unroll
    for (int o = 16; o; o >>= 1) s += __shfl_xor_sync(0xffffffffu, s, o);
    if (lane == 0) atomicAdd(&g_loss, (double)s);
}

__global__ void final_k(float* __restrict__ out) {
    __shared__ double red[32];
    int t = threadIdx.x;
    double p = (double)g_cnt[t] / (double)NTOK;
    double v = p * log(p + 1e-10);
#pragma unroll
    for (int o = 16; o; o >>= 1) v += __shfl_xor_sync(0xffffffffu, v, o);
    if ((t & 31) == 0) red[t >> 5] = v;
    __syncthreads();
    if (t < 32) {
        double w = red[t];
#pragma unroll
        for (int o = 16; o; o >>= 1) w += __shfl_xor_sync(0xffffffffu, w, o);
        if (t == 0) {
            out[PERPOFF] = (float)exp(-w);
            out[0] = (float)(0.25 * g_loss / (double)((long long)NTOK * DDIM));
        }
    }
}

// ---------------------------------------------------------------------------
extern "C" void kernel_launch(void* const* d_in, const int* in_sizes, int n_in,
                              void* d_out, int out_size) {
    const float* x = (const float*)d_in[0];   // inputs  [64,2048,256]
    const float* W = (const float*)d_in[1];   // pre_w   [256,256]
    const float* b = (const float*)d_in[2];   // pre_b   [256]
    const float* E = (const float*)d_in[3];   // emb     [1024,256]
    float* out = (float*)d_out;

    cudaFuncSetAttribute(vq_main, cudaFuncAttributeMaxDynamicSharedMemorySize, SMEM_BYTES);

    init_k<<<1, 1024>>>();
    enorm_k<<<KCODE, 32>>>(E);
    vq_main<<<NTOK / 128, 256, SMEM_BYTES>>>(x, W, b, E);
    enc_zero<<<8192, 256>>>(out);
    enc_ones<<<NTOK / 256, 256>>>(out);
    quant_loss<<<NTOK / 8, 256>>>(out, x, E);
    final_k<<<1, 1024>>>(out);
}

// round 8
// speedup vs baseline: 1.0008x; 1.0008x over previous
#include <cuda_runtime.h>

// ---------------------------------------------------------------------------
// VQ (vector-quantization) forward:
//   f = x @ W^T + b                       [N, 256]
//   idx = argmin_k ||f - e_k||^2          [N]     (K = 1024 codes)
//   quantized_st = x + (e[idx] - x)       [N, 256]
//   loss = 0.25 * mean((e[idx] - x)^2)
//   perplexity = exp(-sum p log(p+1e-10)), p = histogram(idx)/N
//   encodings = one_hot(idx, K) f32       [N, K]
//
// Output layout (flattened tuple): [loss(1) | quantized(N*256) | perp(1) | enc(N*K)]
// ---------------------------------------------------------------------------

#define NTOK   (64 * 2048)         // 131072
#define DDIM   256
#define KCODE  1024
#define QOFF   1
#define PERPOFF (1 + NTOK * DDIM)  // 33554433
#define ENCOFF  (PERPOFF + 1)      // 33554434

// scratch (static device globals: no runtime allocation)
__device__ float  g_enorm[KCODE];
__device__ int    g_idx[NTOK];
__device__ int    g_cnt[KCODE];
__device__ double g_loss;

typedef unsigned long long u64;

// ---- packed f32x2 helpers (Blackwell FFMA2: 2x fp32 FMA throughput) -------
__device__ __forceinline__ u64 pk2(float lo, float hi) {
    u64 r; asm("mov.b64 %0, {%1,%2};" : "=l"(r) : "f"(lo), "f"(hi)); return r;
}
__device__ __forceinline__ u64 ffma2(u64 a, u64 b, u64 c) {
    u64 d; asm("fma.rn.f32x2 %0, %1, %2, %3;" : "=l"(d) : "l"(a), "l"(b), "l"(c)); return d;
}
__device__ __forceinline__ float2 upk2(u64 v) {
    float lo, hi; asm("mov.b64 {%0,%1}, %2;" : "=f"(lo), "=f"(hi) : "l"(v));
    return make_float2(lo, hi);
}

// ---- shared-memory layout for the fused kernel ----------------------------
#define SPITCH       132                       // padded pitch (floats) to dodge bank conflicts
#define FS_FLOATS    (256 * SPITCH)            // resident f tile, stored [k][m]
#define STAGE_FLOATS (16 * SPITCH)             // one 128x16 stage tile, stored [k][row]
#define SMEM_FLOATS  (FS_FLOATS + 2 * STAGE_FLOATS + 128)
#define SMEM_BYTES   (SMEM_FLOATS * 4)

// Load a 128-row x 16-col tile (row stride DDIM) into registers: 2x float4/thread.
__device__ __forceinline__ void ldg_tile(const float* __restrict__ src, int tid,
                                         float4& v0, float4& v1) {
    int r0 = tid >> 2, c0 = (tid & 3) << 2;
    v0 = *reinterpret_cast<const float4*>(src + r0 * DDIM + c0);
    int id1 = tid + 256;
    int r1 = id1 >> 2, c1 = (id1 & 3) << 2;
    v1 = *reinterpret_cast<const float4*>(src + r1 * DDIM + c1);
}
// Store those registers transposed into smem stage tile S[k][row] (pitch SPITCH).
__device__ __forceinline__ void sts_tile(float* S, int tid,
                                         const float4& v0, const float4& v1) {
    int r0 = tid >> 2, c0 = (tid & 3) << 2;
    S[(c0 + 0) * SPITCH + r0] = v0.x;
    S[(c0 + 1) * SPITCH + r0] = v0.y;
    S[(c0 + 2) * SPITCH + r0] = v0.z;
    S[(c0 + 3) * SPITCH + r0] = v0.w;
    int id1 = tid + 256;
    int r1 = id1 >> 2, c1 = (id1 & 3) << 2;
    S[(c1 + 0) * SPITCH + r1] = v1.x;
    S[(c1 + 1) * SPITCH + r1] = v1.y;
    S[(c1 + 2) * SPITCH + r1] = v1.z;
    S[(c1 + 3) * SPITCH + r1] = v1.w;
}

// One k-step of the 8x8 micro-tile (packed over column pairs): 32 FFMA2 = 64 FMA.
__device__ __forceinline__ void mm_step(const float* __restrict__ a_row,
                                        const float* __restrict__ b_row,
                                        int ty8, int tx8, u64* acc) {
    float4 aA = *reinterpret_cast<const float4*>(a_row + ty8);
    float4 aB = *reinterpret_cast<const float4*>(a_row + ty8 + 4);
    float4 bA = *reinterpret_cast<const float4*>(b_row + tx8);
    float4 bB = *reinterpret_cast<const float4*>(b_row + tx8 + 4);
    u64 b2[4];
    b2[0] = pk2(bA.x, bA.y); b2[1] = pk2(bA.z, bA.w);
    b2[2] = pk2(bB.x, bB.y); b2[3] = pk2(bB.z, bB.w);
    float av[8] = {aA.x, aA.y, aA.z, aA.w, aB.x, aB.y, aB.z, aB.w};
#pragma unroll
    for (int i = 0; i < 8; i++) {
        u64 aa = pk2(av[i], av[i]);
#pragma unroll
        for (int j = 0; j < 4; j++) acc[i * 4 + j] = ffma2(aa, b2[j], acc[i * 4 + j]);
    }
}

// ---------------------------------------------------------------------------
// Fused kernel: per CTA of 128 tokens:
//   phase 1: f tile = x @ W^T + b  (resident in smem, transposed [k][m])
//   phase 2: distances vs all 1024 codes, argmin with first-index tie-break,
//            histogram atomics.
// ---------------------------------------------------------------------------
__global__ void __launch_bounds__(256, 1)
vq_main(const float* __restrict__ x, const float* __restrict__ W,
        const float* __restrict__ bias, const float* __restrict__ E) {
    extern __shared__ float sm[];
    float* f_s  = sm;                          // [256][SPITCH]
    float* As   = sm + FS_FLOATS;              // [16][SPITCH]
    float* Bs   = As + STAGE_FLOATS;           // [16][SPITCH]
    float* f2_s = Bs + STAGE_FLOATS;           // [128]

    const int tid = threadIdx.x;
    const int tx = tid & 15, ty = tid >> 4;
    const int tx8 = tx * 8, ty8 = ty * 8;
    const int row0 = blockIdx.x * 128;
    const float* xbase = x + (size_t)row0 * DDIM;

    // ---------------- phase 1: pre-linear ----------------
#pragma unroll 1
    for (int jt = 0; jt < 2; jt++) {
        u64 acc[32];
#pragma unroll
        for (int i = 0; i < 32; i++) acc[i] = 0ull;
        const float* wsrc = W + (size_t)jt * 128 * DDIM;
        float4 a0, a1, b0, b1;
        ldg_tile(xbase, tid, a0, a1);
        ldg_tile(wsrc, tid, b0, b1);
#pragma unroll 1
        for (int s = 0; s < 16; s++) {
            __syncthreads();
            sts_tile(As, tid, a0, a1);
            sts_tile(Bs, tid, b0, b1);
            if (s < 15) {
                ldg_tile(xbase + (s + 1) * 16, tid, a0, a1);
                ldg_tile(wsrc + (s + 1) * 16, tid, b0, b1);
            }
            __syncthreads();
#pragma unroll
            for (int kk = 0; kk < 16; kk++)
                mm_step(As + kk * SPITCH, Bs + kk * SPITCH, ty8, tx8, acc);
        }
        // epilogue: f_s[col][row] = acc + bias
        float4 bb0 = *reinterpret_cast<const float4*>(bias + jt * 128 + tx8);
        float4 bb1 = *reinterpret_cast<const float4*>(bias + jt * 128 + tx8 + 4);
        float bv[8] = {bb0.x, bb0.y, bb0.z, bb0.w, bb1.x, bb1.y, bb1.z, bb1.w};
#pragma unroll
        for (int i = 0; i < 8; i++) {
            int row = ty8 + i;
#pragma unroll
            for (int jp = 0; jp < 4; jp++) {
                float2 v = upk2(acc[i * 4 + jp]);
                int c = jt * 128 + tx8 + jp * 2;
                f_s[(c + 0) * SPITCH + row] = v.x + bv[jp * 2 + 0];
                f_s[(c + 1) * SPITCH + row] = v.y + bv[jp * 2 + 1];
            }
        }
    }
    __syncthreads();

    // per-token ||f||^2
    if (tid < 128) {
        float s = 0.0f;
        for (int k = 0; k < 256; k++) {
            float v = f_s[k * SPITCH + tid];
            s = __fmaf_rn(v, v, s);
        }
        f2_s[tid] = s;
    }
    __syncthreads();

    // ---------------- phase 2: distances + argmin ----------------
    float bestv[8];
    int besti[8];
#pragma unroll
    for (int i = 0; i < 8; i++) { bestv[i] = 3.4e38f; besti[i] = 0; }

#pragma unroll 1
    for (int nt = 0; nt < 8; nt++) {
        u64 acc[32];
#pragma unroll
        for (int i = 0; i < 32; i++) acc[i] = 0ull;
        const float* esrc = E + (size_t)nt * 128 * DDIM;
        float4 b0, b1;
        ldg_tile(esrc, tid, b0, b1);
#pragma unroll 1
        for (int s = 0; s < 16; s++) {
            __syncthreads();
            sts_tile(Bs, tid, b0, b1);
            if (s < 15) ldg_tile(esrc + (s + 1) * 16, tid, b0, b1);
            __syncthreads();
#pragma unroll
            for (int kk = 0; kk < 16; kk++)
                mm_step(f_s + (s * 16 + kk) * SPITCH, Bs + kk * SPITCH, ty8, tx8, acc);
        }
        // epilogue: d = (||f||^2 + ||e||^2) - 2*dot  (match reference rounding)
        float4 e0 = *reinterpret_cast<const float4*>(g_enorm + nt * 128 + tx8);
        float4 e1 = *reinterpret_cast<const float4*>(g_enorm + nt * 128 + tx8 + 4);
        float en[8] = {e0.x, e0.y, e0.z, e0.w, e1.x, e1.y, e1.z, e1.w};
#pragma unroll
        for (int i = 0; i < 8; i++) {
            float f2 = f2_s[ty8 + i];
#pragma unroll
            for (int jp = 0; jp < 4; jp++) {
                float2 v = upk2(acc[i * 4 + jp]);
                int c = nt * 128 + tx8 + jp * 2;
                float d0 = __fsub_rn(__fadd_rn(f2, en[jp * 2 + 0]), __fmul_rn(2.0f, v.x));
                float d1 = __fsub_rn(__fadd_rn(f2, en[jp * 2 + 1]), __fmul_rn(2.0f, v.y));
                if (d0 < bestv[i]) { bestv[i] = d0; besti[i] = c; }
                if (d1 < bestv[i]) { bestv[i] = d1; besti[i] = c + 1; }
            }
        }
    }

    // reduce across the 16 tx threads holding the same 8 tokens (within warp half)
#pragma unroll
    for (int i = 0; i < 8; i++) {
        float v = bestv[i];
        int ix = besti[i];
#pragma unroll
        for (int o = 8; o; o >>= 1) {
            float ov = __shfl_xor_sync(0xffffffffu, v, o);
            int   oi = __shfl_xor_sync(0xffffffffu, ix, o);
            if (ov < v || (ov == v && oi < ix)) { v = ov; ix = oi; }
        }
        if (tx == 0) {
            int token = row0 + ty8 + i;
            g_idx[token] = ix;
            atomicAdd(&g_cnt[ix], 1);
        }
    }
}

// ---------------------------------------------------------------------------
// Small kernels
// ---------------------------------------------------------------------------
__global__ void init_k() {
    int t = threadIdx.x;
    if (t < KCODE) g_cnt[t] = 0;
    if (t == 0) g_loss = 0.0;
}

__global__ void enorm_k(const float* __restrict__ E) {
    int k = blockIdx.x, lane = threadIdx.x;
    const float4* e4 = reinterpret_cast<const float4*>(E + (size_t)k * DDIM);
    float4 a = e4[lane * 2], b = e4[lane * 2 + 1];
    float s = a.x * a.x + a.y * a.y + a.z * a.z + a.w * a.w
            + b.x * b.x + b.y * b.y + b.z * b.z + b.w * b.w;
#pragma unroll
    for (int o = 16; o; o >>= 1) s += __shfl_xor_sync(0xffffffffu, s, o);
    if (lane == 0) g_enorm[k] = s;
}

__global__ void enc_zero(float* __restrict__ out) {
    float2* p = reinterpret_cast<float2*>(out + ENCOFF);  // even offset -> 8B aligned
    long long n = (long long)NTOK * KCODE / 2;
    long long i = (long long)blockIdx.x * blockDim.x + threadIdx.x;
    long long stride = (long long)gridDim.x * blockDim.x;
    float2 z = make_float2(0.0f, 0.0f);
    for (; i < n; i += stride) p[i] = z;
}

__global__ void enc_ones(float* __restrict__ out) {
    int n = blockIdx.x * blockDim.x + threadIdx.x;
    if (n < NTOK) out[(long long)ENCOFF + (long long)n * KCODE + g_idx[n]] = 1.0f;
}

__global__ void quant_loss(float* __restrict__ out, const float* __restrict__ x,
                           const float* __restrict__ E) {
    int warp = (blockIdx.x * blockDim.x + threadIdx.x) >> 5;
    int lane = threadIdx.x & 31;
    if (warp >= NTOK) return;
    int c = g_idx[warp];
    const float4* e4 = reinterpret_cast<const float4*>(E + (size_t)c * DDIM);
    const float4* x4 = reinterpret_cast<const float4*>(x + (size_t)warp * DDIM);
    float4 e0 = e4[lane * 2], e1 = e4[lane * 2 + 1];
    float4 v0 = x4[lane * 2], v1 = x4[lane * 2 + 1];
    float* q = out + QOFF + (size_t)warp * DDIM + lane * 8;
    float s = 0.0f, d;
    d = __fsub_rn(e0.x, v0.x); q[0] = __fadd_rn(v0.x, d); s = __fmaf_rn(d, d, s);
    d = __fsub_rn(e0.y, v0.y); q[1] = __fadd_rn(v0.y, d); s = __fmaf_rn(d, d, s);
    d = __fsub_rn(e0.z, v0.z); q[2] = __fadd_rn(v0.z, d); s = __fmaf_rn(d, d, s);
    d = __fsub_rn(e0.w, v0.w); q[3] = __fadd_rn(v0.w, d); s = __fmaf_rn(d, d, s);
    d = __fsub_rn(e1.x, v1.x); q[4] = __fadd_rn(v1.x, d); s = __fmaf_rn(d, d, s);
    d = __fsub_rn(e1.y, v1.y); q[5] = __fadd_rn(v1.y, d); s = __fmaf_rn(d, d, s);
    d = __fsub_rn(e1.z, v1.z); q[6] = __fadd_rn(v1.z, d); s = __fmaf_rn(d, d, s);
    d = __fsub_rn(e1.w, v1.w); q[7] = __fadd_rn(v1.w, d); s = __fmaf_rn(d, d, s);
#pragma unroll
    for (int o = 16; o; o >>= 1) s += __shfl_xor_sync(0xffffffffu, s, o);
    if (lane == 0) atomicAdd(&g_loss, (double)s);
}

__global__ void final_k(float* __restrict__ out) {
    __shared__ double red[32];
    int t = threadIdx.x;
    double p = (double)g_cnt[t] / (double)NTOK;
    double v = p * log(p + 1e-10);
#pragma unroll
    for (int o = 16; o; o >>= 1) v += __shfl_xor_sync(0xffffffffu, v, o);
    if ((t & 31) == 0) red[t >> 5] = v;
    __syncthreads();
    if (t < 32) {
        double w = red[t];
#pragma unroll
        for (int o = 16; o; o >>= 1) w += __shfl_xor_sync(0xffffffffu, w, o);
        if (t == 0) {
            out[PERPOFF] = (float)exp(-w);
            out[0] = (float)(0.25 * g_loss / (double)((long long)NTOK * DDIM));
        }
    }
}

// ---------------------------------------------------------------------------
extern "C" void kernel_launch(void* const* d_in, const int* in_sizes, int n_in,
                              void* d_out, int out_size) {
    const float* x = (const float*)d_in[0];   // inputs  [64,2048,256]
    const float* W = (const float*)d_in[1];   // pre_w   [256,256]
    const float* b = (const float*)d_in[2];   // pre_b   [256]
    const float* E = (const float*)d_in[3];   // emb     [1024,256]
    float* out = (float*)d_out;

    cudaFuncSetAttribute(vq_main, cudaFuncAttributeMaxDynamicSharedMemorySize, SMEM_BYTES);

    init_k<<<1, 1024>>>();
    enorm_k<<<KCODE, 32>>>(E);
    vq_main<<<NTOK / 128, 256, SMEM_BYTES>>>(x, W, b, E);
    enc_zero<<<8192, 256>>>(out);
    enc_ones<<<NTOK / 256, 256>>>(out);
    quant_loss<<<NTOK / 8, 256>>>(out, x, E);
    final_k<<<1, 1024>>>(out);
}

// round 12
// speedup vs baseline: 1.6560x; 1.6546x over previous
#include <cuda_runtime.h>
#include <cuda_fp16.h>

// ---------------------------------------------------------------------------
// VQ forward. Output: [loss(1) | quantized(N*256) | perp(1) | enc(N*K)]
// ---------------------------------------------------------------------------
#define NTOK   (64 * 2048)         // 131072
#define DDIM   256
#define KCODE  1024
#define QOFF   1
#define PERPOFF (1 + NTOK * DDIM)
#define ENCOFF  (PERPOFF + 1)

typedef unsigned long long u64;
typedef unsigned int u32;

// scratch (static device globals)
__device__ float  g_enorm[KCODE];
__device__ int    g_idx[NTOK];
__device__ int    g_cnt[KCODE];
__device__ double g_loss;
__device__ __align__(16) u32 g_Eh16[KCODE * 128];   // fp16x2 high limbs of emb
__device__ __align__(16) u32 g_El16[KCODE * 128];   // fp16x2 low  limbs of emb

// ---- packed f32x2 helpers (FFMA2 phase-1 path, proven in R4) --------------
__device__ __forceinline__ u64 pk2(float lo, float hi) {
    u64 r; asm("mov.b64 %0, {%1,%2};" : "=l"(r) : "f"(lo), "f"(hi)); return r;
}
__device__ __forceinline__ u64 ffma2(u64 a, u64 b, u64 c) {
    u64 d; asm("fma.rn.f32x2 %0, %1, %2, %3;" : "=l"(d) : "l"(a), "l"(b), "l"(c)); return d;
}
__device__ __forceinline__ float2 upk2(u64 v) {
    float lo, hi; asm("mov.b64 {%0,%1}, %2;" : "=f"(lo), "=f"(hi) : "l"(v));
    return make_float2(lo, hi);
}
__device__ __forceinline__ u32 pkh(__half a, __half b) {
    return (u32)__half_as_ushort(a) | ((u32)__half_as_ushort(b) << 16);
}

// ---- mma.sync m16n8k16 f16 -> f32 (plain sm_80+ PTX, no 'a' features) -----
__device__ __forceinline__ void mma16816(float* c, u32 a0, u32 a1, u32 a2, u32 a3,
                                         u32 b0, u32 b1) {
    asm volatile(
        "mma.sync.aligned.m16n8k16.row.col.f32.f16.f16.f32 "
        "{%0,%1,%2,%3}, {%4,%5,%6,%7}, {%8,%9}, {%0,%1,%2,%3};"
        : "+f"(c[0]), "+f"(c[1]), "+f"(c[2]), "+f"(c[3])
        : "r"(a0), "r"(a1), "r"(a2), "r"(a3), "r"(b0), "r"(b1));
}

// ---- shared-memory layout -------------------------------------------------
#define SPITCH     132
#define OFF_F2     0                     // 128 floats
#define OFF_EN     512                   // 256 floats (nt-parity double buffer)
#define OFF_A      1536                  // Ah: 128 rows x 132 u32 pitch
#define A_BYTES    (128 * 132 * 4)       // 67584
#define OFF_AL     (OFF_A + A_BYTES)     // Al
#define OFF_BST    (OFF_AL + A_BYTES)    // 136704: B stage, 2 bufs x 2 limbs
#define BST_LIMB_W 4608                  // 128 x 36 u32
#define BST_BUF_W  (2 * BST_LIMB_W)      // 9216 u32 per buffer
#define SMEM_TOTAL (OFF_BST + 2 * BST_BUF_W * 4)   // 210432 B

// ---- FFMA2 phase-1 tile helpers (verbatim R4) -----------------------------
__device__ __forceinline__ void ldg_tile(const float* __restrict__ src, int tid,
                                         float4& v0, float4& v1) {
    int r0 = tid >> 2, c0 = (tid & 3) << 2;
    v0 = *reinterpret_cast<const float4*>(src + r0 * DDIM + c0);
    int id1 = tid + 256;
    int r1 = id1 >> 2, c1 = (id1 & 3) << 2;
    v1 = *reinterpret_cast<const float4*>(src + r1 * DDIM + c1);
}
__device__ __forceinline__ void sts_tile(float* S, int tid,
                                         const float4& v0, const float4& v1) {
    int r0 = tid >> 2, c0 = (tid & 3) << 2;
    S[(c0 + 0) * SPITCH + r0] = v0.x; S[(c0 + 1) * SPITCH + r0] = v0.y;
    S[(c0 + 2) * SPITCH + r0] = v0.z; S[(c0 + 3) * SPITCH + r0] = v0.w;
    int id1 = tid + 256;
    int r1 = id1 >> 2, c1 = (id1 & 3) << 2;
    S[(c1 + 0) * SPITCH + r1] = v1.x; S[(c1 + 1) * SPITCH + r1] = v1.y;
    S[(c1 + 2) * SPITCH + r1] = v1.z; S[(c1 + 3) * SPITCH + r1] = v1.w;
}
__device__ __forceinline__ void mm_step(const float* __restrict__ a_row,
                                        const float* __restrict__ b_row,
                                        int ty8, int tx8, u64* acc) {
    float4 aA = *reinterpret_cast<const float4*>(a_row + ty8);
    float4 aB = *reinterpret_cast<const float4*>(a_row + ty8 + 4);
    float4 bA = *reinterpret_cast<const float4*>(b_row + tx8);
    float4 bB = *reinterpret_cast<const float4*>(b_row + tx8 + 4);
    u64 b2[4];
    b2[0] = pk2(bA.x, bA.y); b2[1] = pk2(bA.z, bA.w);
    b2[2] = pk2(bB.x, bB.y); b2[3] = pk2(bB.z, bB.w);
    float av[8] = {aA.x, aA.y, aA.z, aA.w, aB.x, aB.y, aB.z, aB.w};
#pragma unroll
    for (int i = 0; i < 8; i++) {
        u64 aa = pk2(av[i], av[i]);
#pragma unroll
        for (int j = 0; j < 4; j++) acc[i * 4 + j] = ffma2(aa, b2[j], acc[i * 4 + j]);
    }
}

// ---------------------------------------------------------------------------
// Main fused kernel. CTA = 128 tokens, 256 threads, 1 CTA/SM.
//  phase 1: f = x@W^T + b (FFMA2, fp32 exact) -> fp16 limbs Ah/Al in smem
//  phase 2: dist GEMM vs 1024 codes: mma.sync f16 (hh+hl+lh), argmin epilogue
// ---------------------------------------------------------------------------
__global__ void __launch_bounds__(256, 1)
vq_main(const float* __restrict__ x, const float* __restrict__ W,
        const float* __restrict__ bias) {
    extern __shared__ char smc[];
    float* f2_s = (float*)(smc + OFF_F2);
    float* en_s = (float*)(smc + OFF_EN);
    u32*   Ah   = (u32*)(smc + OFF_A);
    u32*   Al   = (u32*)(smc + OFF_AL);
    u32*   Bst  = (u32*)(smc + OFF_BST);
    float* As   = (float*)(smc + OFF_BST);              // phase-1 staging reuse
    float* Bs   = As + 16 * SPITCH;

    const int tid = threadIdx.x;
    const int tx = tid & 15, ty = tid >> 4;
    const int tx8 = tx * 8, ty8 = ty * 8;
    const int row0 = blockIdx.x * 128;
    const float* xbase = x + (size_t)row0 * DDIM;

    // ================= phase 1: pre-linear (FFMA2, fp32) ===================
#pragma unroll 1
    for (int jt = 0; jt < 2; jt++) {
        u64 acc[32];
#pragma unroll
        for (int i = 0; i < 32; i++) acc[i] = 0ull;
        const float* wsrc = W + (size_t)jt * 128 * DDIM;
        float4 a0, a1, b0, b1;
        ldg_tile(xbase, tid, a0, a1);
        ldg_tile(wsrc, tid, b0, b1);
#pragma unroll 1
        for (int s = 0; s < 16; s++) {
            __syncthreads();
            sts_tile(As, tid, a0, a1);
            sts_tile(Bs, tid, b0, b1);
            if (s < 15) {
                ldg_tile(xbase + (s + 1) * 16, tid, a0, a1);
                ldg_tile(wsrc + (s + 1) * 16, tid, b0, b1);
            }
            __syncthreads();
#pragma unroll
            for (int kk = 0; kk < 16; kk++)
                mm_step(As + kk * SPITCH, Bs + kk * SPITCH, ty8, tx8, acc);
        }
        // epilogue: bias, ||f||^2 partials, fp16 limb split -> Ah/Al[m][k]
        float4 bb0 = *reinterpret_cast<const float4*>(bias + jt * 128 + tx8);
        float4 bb1 = *reinterpret_cast<const float4*>(bias + jt * 128 + tx8 + 4);
        float bv[8] = {bb0.x, bb0.y, bb0.z, bb0.w, bb1.x, bb1.y, bb1.z, bb1.w};
        float rsq[8];
#pragma unroll
        for (int i = 0; i < 8; i++) {
            int r = ty8 + i;
            float rs = 0.0f;
#pragma unroll
            for (int jp = 0; jp < 4; jp++) {
                float2 v = upk2(acc[i * 4 + jp]);
                float v0 = v.x + bv[jp * 2 + 0];
                float v1 = v.y + bv[jp * 2 + 1];
                rs = __fmaf_rn(v0, v0, rs);
                rs = __fmaf_rn(v1, v1, rs);
                __half h0 = __float2half_rn(v0);
                __half l0 = __float2half_rn(v0 - __half2float(h0));
                __half h1 = __float2half_rn(v1);
                __half l1 = __float2half_rn(v1 - __half2float(h1));
                int w = r * 132 + jt * 64 + tx * 4 + jp;
                Ah[w] = pkh(h0, h1);
                Al[w] = pkh(l0, l1);
            }
            rsq[i] = rs;
        }
#pragma unroll
        for (int i = 0; i < 8; i++) {
#pragma unroll
            for (int o = 8; o; o >>= 1)
                rsq[i] += __shfl_xor_sync(0xffffffffu, rsq[i], o);
        }
        if (tx == 0) {
#pragma unroll
            for (int i = 0; i < 8; i++) {
                if (jt == 0) f2_s[ty8 + i] = rsq[i];
                else         f2_s[ty8 + i] += rsq[i];
            }
        }
    }
    __syncthreads();   // Ah/Al + f2_s visible; phase-1 staging region now free

    // ================= phase 2: HMMA distance GEMM + argmin ================
    const int lane = tid & 31, wrp = tid >> 5;
    const int g4 = lane >> 2, t4 = lane & 3;
    const int rowA = wrp * 16 + g4, rowB = rowA + 8;
    const float f2a = f2_s[rowA], f2b = f2_s[rowB];

    float accf[64];
#pragma unroll
    for (int i = 0; i < 64; i++) accf[i] = 0.0f;
    float bestA = 3.4e38f, bestB = 3.4e38f;
    int ibA = 0, ibB = 0;

    const int er = tid >> 1, eh = tid & 1;     // stage-copy mapping
    const uint4* EH4 = (const uint4*)g_Eh16;
    const uint4* EL4 = (const uint4*)g_El16;

    // prologue: stage chunk 0 into buffer 0, stage enorm tile 0
    uint4 pre[8];
    {
        size_t bi = (size_t)er * 32 + eh * 4;  // nt=0, kc=0
        pre[0] = EH4[bi]; pre[1] = EH4[bi + 1]; pre[2] = EH4[bi + 2]; pre[3] = EH4[bi + 3];
        pre[4] = EL4[bi]; pre[5] = EL4[bi + 1]; pre[6] = EL4[bi + 2]; pre[7] = EL4[bi + 3];
        u32* d0 = Bst + er * 36 + eh * 16;
        ((uint4*)d0)[0] = pre[0]; ((uint4*)d0)[1] = pre[1];
        ((uint4*)d0)[2] = pre[2]; ((uint4*)d0)[3] = pre[3];
        u32* d1 = d0 + BST_LIMB_W;
        ((uint4*)d1)[0] = pre[4]; ((uint4*)d1)[1] = pre[5];
        ((uint4*)d1)[2] = pre[6]; ((uint4*)d1)[3] = pre[7];
        if (tid < 128) en_s[tid] = g_enorm[tid];
    }
    __syncthreads();

#pragma unroll 1
    for (int s = 0; s < 32; s++) {
        const int nt = s >> 2, kc = s & 3, buf = s & 1;
        // prefetch next chunk (LDG latency hidden behind the MMAs)
        if (s < 31) {
            int nn = (s + 1) >> 2, nk = (s + 1) & 3;
            size_t bi = (size_t)(nn * 128 + er) * 32 + nk * 8 + eh * 4;
            pre[0] = EH4[bi]; pre[1] = EH4[bi + 1]; pre[2] = EH4[bi + 2]; pre[3] = EH4[bi + 3];
            pre[4] = EL4[bi]; pre[5] = EL4[bi + 1]; pre[6] = EL4[bi + 2]; pre[7] = EL4[bi + 3];
        }
        float enx = 0.0f;
        if (kc == 3 && nt < 7 && tid < 128) enx = g_enorm[(nt + 1) * 128 + tid];

        // MMAs on current buffer: (Ah,Bh) + (Ah,Bl) + (Al,Bh)
        const u32* bh = Bst + buf * BST_BUF_W;
        const u32* bl = bh + BST_LIMB_W;
#pragma unroll
        for (int kk = 0; kk < 4; kk++) {
            // A k-pair index must include this stage's k-chunk offset kc*32
            // (R11 bug: missing kc*32 made every chunk reuse f's k=0..63)
            int a0i = rowA * 132 + kc * 32 + kk * 8 + t4;
            int a1i = rowB * 132 + kc * 32 + kk * 8 + t4;
            u32 ah0 = Ah[a0i], ah1 = Ah[a1i], ah2 = Ah[a0i + 4], ah3 = Ah[a1i + 4];
            u32 al0 = Al[a0i], al1 = Al[a1i], al2 = Al[a0i + 4], al3 = Al[a1i + 4];
#pragma unroll
            for (int j = 0; j < 16; j++) {
                int bidx = (j * 8 + g4) * 36 + kk * 8 + t4;
                u32 b0 = bh[bidx], b1 = bh[bidx + 4];
                u32 c0 = bl[bidx], c1 = bl[bidx + 4];
                mma16816(accf + j * 4, ah0, ah1, ah2, ah3, b0, b1);
                mma16816(accf + j * 4, ah0, ah1, ah2, ah3, c0, c1);
                mma16816(accf + j * 4, al0, al1, al2, al3, b0, b1);
            }
        }
        // store prefetched chunk into the other buffer
        if (s < 31) {
            u32* d0 = Bst + (buf ^ 1) * BST_BUF_W + er * 36 + eh * 16;
            ((uint4*)d0)[0] = pre[0]; ((uint4*)d0)[1] = pre[1];
            ((uint4*)d0)[2] = pre[2]; ((uint4*)d0)[3] = pre[3];
            u32* d1 = d0 + BST_LIMB_W;
            ((uint4*)d1)[0] = pre[4]; ((uint4*)d1)[1] = pre[5];
            ((uint4*)d1)[2] = pre[6]; ((uint4*)d1)[3] = pre[7];
        }
        if (kc == 3 && nt < 7 && tid < 128)
            en_s[((nt + 1) & 1) * 128 + tid] = enx;
        __syncthreads();

        // per-N-tile argmin epilogue (regs only; overlaps other warps' MMAs)
        if (kc == 3) {
            const float* ens = en_s + (nt & 1) * 128;
#pragma unroll
            for (int j = 0; j < 16; j++) {
                int cl = j * 8 + 2 * t4;
                float e0 = ens[cl], e1 = ens[cl + 1];
                int col = nt * 128 + cl;
                float d;
                d = __fsub_rn(__fadd_rn(f2a, e0), __fmul_rn(2.0f, accf[j * 4 + 0]));
                if (d < bestA) { bestA = d; ibA = col; }
                d = __fsub_rn(__fadd_rn(f2a, e1), __fmul_rn(2.0f, accf[j * 4 + 1]));
                if (d < bestA) { bestA = d; ibA = col + 1; }
                d = __fsub_rn(__fadd_rn(f2b, e0), __fmul_rn(2.0f, accf[j * 4 + 2]));
                if (d < bestB) { bestB = d; ibB = col; }
                d = __fsub_rn(__fadd_rn(f2b, e1), __fmul_rn(2.0f, accf[j * 4 + 3]));
                if (d < bestB) { bestB = d; ibB = col + 1; }
                accf[j * 4 + 0] = 0.0f; accf[j * 4 + 1] = 0.0f;
                accf[j * 4 + 2] = 0.0f; accf[j * 4 + 3] = 0.0f;
            }
        }
    }

    // reduce argmin across the 4 t4-lanes sharing each row (first-index ties)
#pragma unroll
    for (int o = 2; o; o >>= 1) {
        float ov = __shfl_xor_sync(0xffffffffu, bestA, o);
        int   oi = __shfl_xor_sync(0xffffffffu, ibA, o);
        if (ov < bestA || (ov == bestA && oi < ibA)) { bestA = ov; ibA = oi; }
        ov = __shfl_xor_sync(0xffffffffu, bestB, o);
        oi = __shfl_xor_sync(0xffffffffu, ibB, o);
        if (ov < bestB || (ov == bestB && oi < ibB)) { bestB = ov; ibB = oi; }
    }
    if (t4 == 0) {
        g_idx[row0 + rowA] = ibA; atomicAdd(&g_cnt[ibA], 1);
        g_idx[row0 + rowB] = ibB; atomicAdd(&g_cnt[ibB], 1);
    }
}

// ---------------------------------------------------------------------------
// Small kernels
// ---------------------------------------------------------------------------
__global__ void init_k() {
    int t = threadIdx.x;
    if (t < KCODE) g_cnt[t] = 0;
    if (t == 0) g_loss = 0.0;
}

// E fp16 limb split + ||e||^2. One block per code, 128 threads (2 elems each).
__global__ void prep_k(const float* __restrict__ E) {
    __shared__ float red[4];
    int k = blockIdx.x, t = threadIdx.x;
    float v0 = E[(size_t)k * DDIM + 2 * t];
    float v1 = E[(size_t)k * DDIM + 2 * t + 1];
    __half h0 = __float2half_rn(v0);
    __half l0 = __float2half_rn(v0 - __half2float(h0));
    __half h1 = __float2half_rn(v1);
    __half l1 = __float2half_rn(v1 - __half2float(h1));
    g_Eh16[k * 128 + t] = pkh(h0, h1);
    g_El16[k * 128 + t] = pkh(l0, l1);
    float s = v0 * v0 + v1 * v1;
#pragma unroll
    for (int o = 16; o; o >>= 1) s += __shfl_xor_sync(0xffffffffu, s, o);
    if ((t & 31) == 0) red[t >> 5] = s;
    __syncthreads();
    if (t == 0) g_enorm[k] = red[0] + red[1] + red[2] + red[3];
}

// fused one-hot writer: one warp per token writes its full 1024-float row
__global__ void enc_k(float* __restrict__ out) {
    int tok = (blockIdx.x * blockDim.x + threadIdx.x) >> 5;
    int lane = threadIdx.x & 31;
    if (tok >= NTOK) return;
    int idx = g_idx[tok];
    float2* row = reinterpret_cast<float2*>(out + ENCOFF + (size_t)tok * KCODE);
#pragma unroll
    for (int q = 0; q < 16; q++) {
        int p = q * 32 + lane;
        float2 v;
        v.x = (2 * p     == idx) ? 1.0f : 0.0f;
        v.y = (2 * p + 1 == idx) ? 1.0f : 0.0f;
        row[p] = v;
    }
}

__global__ void quant_loss(float* __restrict__ out, const float* __restrict__ x,
                           const float* __restrict__ E) {
    int warp = (blockIdx.x * blockDim.x + threadIdx.x) >> 5;
    int lane = threadIdx.x & 31;
    if (warp >= NTOK) return;
    int c = g_idx[warp];
    const float4* e4 = reinterpret_cast<const float4*>(E + (size_t)c * DDIM);
    const float4* x4 = reinterpret_cast<const float4*>(x + (size_t)warp * DDIM);
    float4 e0 = e4[lane * 2], e1 = e4[lane * 2 + 1];
    float4 v0 = x4[lane * 2], v1 = x4[lane * 2 + 1];
    float* q = out + QOFF + (size_t)warp * DDIM + lane * 8;
    float s = 0.0f, d;
    d = __fsub_rn(e0.x, v0.x); q[0] = __fadd_rn(v0.x, d); s = __fmaf_rn(d, d, s);
    d = __fsub_rn(e0.y, v0.y); q[1] = __fadd_rn(v0.y, d); s = __fmaf_rn(d, d, s);
    d = __fsub_rn(e0.z, v0.z); q[2] = __fadd_rn(v0.z, d); s = __fmaf_rn(d, d, s);
    d = __fsub_rn(e0.w, v0.w); q[3] = __fadd_rn(v0.w, d); s = __fmaf_rn(d, d, s);
    d = __fsub_rn(e1.x, v1.x); q[4] = __fadd_rn(v1.x, d); s = __fmaf_rn(d, d, s);
    d = __fsub_rn(e1.y, v1.y); q[5] = __fadd_rn(v1.y, d); s = __fmaf_rn(d, d, s);
    d = __fsub_rn(e1.z, v1.z); q[6] = __fadd_rn(v1.z, d); s = __fmaf_rn(d, d, s);
    d = __fsub_rn(e1.w, v1.w); q[7] = __fadd_rn(v1.w, d); s = __fmaf_rn(d, d, s);
#pragma unroll
    for (int o = 16; o; o >>= 1) s += __shfl_xor_sync(0xffffffffu, s, o);
    if (lane == 0) atomicAdd(&g_loss, (double)s);
}

__global__ void final_k(float* __restrict__ out) {
    __shared__ double red[32];
    int t = threadIdx.x;
    double p = (double)g_cnt[t] / (double)NTOK;
    double v = p * log(p + 1e-10);
#pragma unroll
    for (int o = 16; o; o >>= 1) v += __shfl_xor_sync(0xffffffffu, v, o);
    if ((t & 31) == 0) red[t >> 5] = v;
    __syncthreads();
    if (t < 32) {
        double w = red[t];
#pragma unroll
        for (int o = 16; o; o >>= 1) w += __shfl_xor_sync(0xffffffffu, w, o);
        if (t == 0) {
            out[PERPOFF] = (float)exp(-w);
            out[0] = (float)(0.25 * g_loss / (double)((long long)NTOK * DDIM));
        }
    }
}

// ---------------------------------------------------------------------------
extern "C" void kernel_launch(void* const* d_in, const int* in_sizes, int n_in,
                              void* d_out, int out_size) {
    const float* x = (const float*)d_in[0];   // inputs  [64,2048,256]
    const float* W = (const float*)d_in[1];   // pre_w   [256,256]
    const float* b = (const float*)d_in[2];   // pre_b   [256]
    const float* E = (const float*)d_in[3];   // emb     [1024,256]
    float* out = (float*)d_out;

    cudaFuncSetAttribute(vq_main, cudaFuncAttributeMaxDynamicSharedMemorySize, SMEM_TOTAL);

    init_k<<<1, 1024>>>();
    prep_k<<<KCODE, 128>>>(E);
    vq_main<<<NTOK / 128, 256, SMEM_TOTAL>>>(x, W, b);
    enc_k<<<NTOK / 8, 256>>>(out);
    quant_loss<<<NTOK / 8, 256>>>(out, x, E);
    final_k<<<1, 1024>>>(out);
}

// round 13
// speedup vs baseline: 1.7930x; 1.0827x over previous
#include <cuda_runtime.h>
#include <cuda_fp16.h>

// ---------------------------------------------------------------------------
// VQ forward. Output: [loss(1) | quantized(N*256) | perp(1) | enc(N*K)]
// ---------------------------------------------------------------------------
#define NTOK   (64 * 2048)         // 131072
#define DDIM   256
#define KCODE  1024
#define QOFF   1
#define PERPOFF (1 + NTOK * DDIM)
#define ENCOFF  (PERPOFF + 1)

typedef unsigned long long u64;
typedef unsigned int u32;

// scratch (static device globals)
__device__ float  g_enorm[KCODE];
__device__ int    g_idx[NTOK];
__device__ int    g_cnt[KCODE];
__device__ double g_loss;
__device__ __align__(16) u32 g_Eh16[KCODE * 128];   // fp16x2 high limbs of emb
__device__ __align__(16) u32 g_El16[KCODE * 128];   // fp16x2 low  limbs of emb
__device__ __align__(16) u32 g_Wh16[DDIM * 128];    // fp16x2 high limbs of pre_w
__device__ __align__(16) u32 g_Wl16[DDIM * 128];    // fp16x2 low  limbs of pre_w

__device__ __forceinline__ u32 pkh(__half a, __half b) {
    return (u32)__half_as_ushort(a) | ((u32)__half_as_ushort(b) << 16);
}

// ---- mma.sync m16n8k16 f16 -> f32 (plain sm_80+ PTX, no 'a' features) -----
__device__ __forceinline__ void mma16816(float* c, u32 a0, u32 a1, u32 a2, u32 a3,
                                         u32 b0, u32 b1) {
    asm volatile(
        "mma.sync.aligned.m16n8k16.row.col.f32.f16.f16.f32 "
        "{%0,%1,%2,%3}, {%4,%5,%6,%7}, {%8,%9}, {%0,%1,%2,%3};"
        : "+f"(c[0]), "+f"(c[1]), "+f"(c[2]), "+f"(c[3])
        : "r"(a0), "r"(a1), "r"(a2), "r"(a3), "r"(b0), "r"(b1));
}

// ---- shared-memory layout -------------------------------------------------
#define OFF_F2     0                     // 128 floats (f2; reused later)
#define OFF_EN     512                   // 256 floats (bias, then enorm 2x128)
#define OFF_A      1536                  // Fh: 128 rows x 132 u32 pitch
#define A_BYTES    (128 * 132 * 4)       // 67584
#define OFF_AL     (OFF_A + A_BYTES)     // Fl
#define OFF_BST    (OFF_AL + A_BYTES)    // 136704: staging region (73728 B)
#define BST_LIMB_W 4608                  // 128 x 36 u32
#define BST_BUF_W  (2 * BST_LIMB_W)      // 9216 u32 per buffer (phase 2)
#define SMEM_TOTAL (OFF_BST + 2 * BST_BUF_W * 4)   // 210432 B

// ---------------------------------------------------------------------------
// Main fused kernel. CTA = 128 tokens, 256 threads, 1 CTA/SM.
//  phase 1: f = x@W^T + b via HMMA fp16 2-limb (x streamed+split in-kernel,
//           W limbs prepped) -> f limbs resident in smem Fh/Fl + f2
//  phase 2: dist GEMM vs 1024 codes: mma.sync (hh+hl+lh), argmin epilogue
// ---------------------------------------------------------------------------
__global__ void __launch_bounds__(256, 1)
vq_main(const float* __restrict__ x, const float* __restrict__ bias) {
    extern __shared__ char smc[];
    float* f2_s = (float*)(smc + OFF_F2);
    float* en_s = (float*)(smc + OFF_EN);
    u32*   Fh   = (u32*)(smc + OFF_A);
    u32*   Fl   = (u32*)(smc + OFF_AL);
    u32*   Bst  = (u32*)(smc + OFF_BST);

    const int tid = threadIdx.x;
    const int lane = tid & 31, wrp = tid >> 5;
    const int g4 = lane >> 2, t4 = lane & 3;
    const int rowA = wrp * 16 + g4, rowB = rowA + 8;
    const int row0 = blockIdx.x * 128;

    // bias into en_s (used by GEMM1 epilogue; phase 2 reuses region for enorm)
    en_s[tid] = bias[tid];

    // ================= phase 1: HMMA pre-linear ============================
    // staging sub-layout (single-buffered): Axh | Axl | Bwh | Bwl
    u32* Axh = Bst;
    u32* Axl = Bst + 4608;
    u32* Bwh = Bst + 9216;
    u32* Bwl = Bst + 13824;

    const int r2 = tid >> 1, eh2 = tid & 1;
    float4 xr[8]; uint4 pw[8];
    {   // prologue: stage 0 (nt2=0, kc=0)
        const float4* xs = (const float4*)(x + (size_t)(row0 + r2) * DDIM + eh2 * 32);
#pragma unroll
        for (int i = 0; i < 8; i++) xr[i] = xs[i];
        const uint4* WH = (const uint4*)g_Wh16;
        const uint4* WL = (const uint4*)g_Wl16;
        size_t wb = (size_t)r2 * 32 + eh2 * 4;
#pragma unroll
        for (int i = 0; i < 4; i++) { pw[i] = WH[wb + i]; pw[4 + i] = WL[wb + i]; }
    }

    float accf[64];
#pragma unroll
    for (int i = 0; i < 64; i++) accf[i] = 0.0f;
    float rsA = 0.0f, rsB = 0.0f;

#pragma unroll 1
    for (int s = 0; s < 8; s++) {
        const int nt2 = s >> 2;
        __syncthreads();               // previous MMAs done reading buffers
        // store x chunk (fp32 regs -> fp16 limbs) and W chunk
        {
            u32* dh = Axh + r2 * 36 + eh2 * 16;
            u32* dl = Axl + r2 * 36 + eh2 * 16;
#pragma unroll
            for (int i = 0; i < 8; i++) {
                float4 v = xr[i];
                __half hx = __float2half_rn(v.x), hy = __float2half_rn(v.y);
                __half hz = __float2half_rn(v.z), hw = __float2half_rn(v.w);
                dh[2 * i]     = pkh(hx, hy);
                dh[2 * i + 1] = pkh(hz, hw);
                dl[2 * i]     = pkh(__float2half_rn(v.x - __half2float(hx)),
                                    __float2half_rn(v.y - __half2float(hy)));
                dl[2 * i + 1] = pkh(__float2half_rn(v.z - __half2float(hz)),
                                    __float2half_rn(v.w - __half2float(hw)));
            }
            uint4* wdh = (uint4*)(Bwh + r2 * 36 + eh2 * 16);
            uint4* wdl = (uint4*)(Bwl + r2 * 36 + eh2 * 16);
#pragma unroll
            for (int i = 0; i < 4; i++) { wdh[i] = pw[i]; wdl[i] = pw[4 + i]; }
        }
        __syncthreads();
        // prefetch next stage into regs (LDG latency hidden behind MMAs)
        if (s < 7) {
            int ns = s + 1, nn2 = ns >> 2, nk = ns & 3;
            const float4* xs = (const float4*)(x + (size_t)(row0 + r2) * DDIM
                                               + nk * 64 + eh2 * 32);
#pragma unroll
            for (int i = 0; i < 8; i++) xr[i] = xs[i];
            const uint4* WH = (const uint4*)g_Wh16;
            const uint4* WL = (const uint4*)g_Wl16;
            size_t wb = (size_t)(nn2 * 128 + r2) * 32 + nk * 8 + eh2 * 4;
#pragma unroll
            for (int i = 0; i < 4; i++) { pw[i] = WH[wb + i]; pw[4 + i] = WL[wb + i]; }
        }
        // MMAs: (Axh,Bwh) + (Axh,Bwl) + (Axl,Bwh)
#pragma unroll
        for (int kk = 0; kk < 4; kk++) {
            int a0i = rowA * 36 + kk * 8 + t4;
            int a1i = rowB * 36 + kk * 8 + t4;
            u32 ah0 = Axh[a0i], ah1 = Axh[a1i], ah2 = Axh[a0i + 4], ah3 = Axh[a1i + 4];
            u32 al0 = Axl[a0i], al1 = Axl[a1i], al2 = Axl[a0i + 4], al3 = Axl[a1i + 4];
#pragma unroll
            for (int j = 0; j < 16; j++) {
                int bidx = (j * 8 + g4) * 36 + kk * 8 + t4;
                u32 b0 = Bwh[bidx], b1 = Bwh[bidx + 4];
                u32 c0 = Bwl[bidx], c1 = Bwl[bidx + 4];
                mma16816(accf + j * 4, ah0, ah1, ah2, ah3, b0, b1);
                mma16816(accf + j * 4, ah0, ah1, ah2, ah3, c0, c1);
                mma16816(accf + j * 4, al0, al1, al2, al3, b0, b1);
            }
        }
        // tile epilogue: bias, ||f||^2 partials, limb split -> Fh/Fl
        if ((s & 3) == 3) {
#pragma unroll
            for (int j = 0; j < 16; j++) {
                int col = nt2 * 128 + j * 8 + 2 * t4;
                float b0f = en_s[col], b1f = en_s[col + 1];
                float v0 = accf[j * 4 + 0] + b0f, v1 = accf[j * 4 + 1] + b1f;
                float v2 = accf[j * 4 + 2] + b0f, v3 = accf[j * 4 + 3] + b1f;
                rsA = __fmaf_rn(v0, v0, rsA); rsA = __fmaf_rn(v1, v1, rsA);
                rsB = __fmaf_rn(v2, v2, rsB); rsB = __fmaf_rn(v3, v3, rsB);
                __half h0 = __float2half_rn(v0), h1 = __float2half_rn(v1);
                __half h2 = __float2half_rn(v2), h3 = __float2half_rn(v3);
                int pA = rowA * 132 + nt2 * 64 + j * 4 + t4;
                int pB = rowB * 132 + nt2 * 64 + j * 4 + t4;
                Fh[pA] = pkh(h0, h1);
                Fl[pA] = pkh(__float2half_rn(v0 - __half2float(h0)),
                             __float2half_rn(v1 - __half2float(h1)));
                Fh[pB] = pkh(h2, h3);
                Fl[pB] = pkh(__float2half_rn(v2 - __half2float(h2)),
                             __float2half_rn(v3 - __half2float(h3)));
                accf[j * 4 + 0] = 0.0f; accf[j * 4 + 1] = 0.0f;
                accf[j * 4 + 2] = 0.0f; accf[j * 4 + 3] = 0.0f;
            }
        }
    }
    // ||f||^2: reduce over the 4 t4 lanes sharing each row
#pragma unroll
    for (int o = 2; o; o >>= 1) {
        rsA += __shfl_xor_sync(0xffffffffu, rsA, o);
        rsB += __shfl_xor_sync(0xffffffffu, rsB, o);
    }
    if (t4 == 0) { f2_s[rowA] = rsA; f2_s[rowB] = rsB; }
    __syncthreads();   // Fh/Fl + f2_s ready; staging region free for phase 2

    // ================= phase 2: HMMA distance GEMM + argmin ================
    const float f2a = f2_s[rowA], f2b = f2_s[rowB];
    float bestA = 3.4e38f, bestB = 3.4e38f;
    int ibA = 0, ibB = 0;

    const int er = tid >> 1, eh = tid & 1;     // stage-copy mapping
    const uint4* EH4 = (const uint4*)g_Eh16;
    const uint4* EL4 = (const uint4*)g_El16;

    // prologue: stage chunk 0 into buffer 0, stage enorm tile 0
    uint4 pre[8];
    {
        size_t bi = (size_t)er * 32 + eh * 4;  // nt=0, kc=0
        pre[0] = EH4[bi]; pre[1] = EH4[bi + 1]; pre[2] = EH4[bi + 2]; pre[3] = EH4[bi + 3];
        pre[4] = EL4[bi]; pre[5] = EL4[bi + 1]; pre[6] = EL4[bi + 2]; pre[7] = EL4[bi + 3];
        u32* d0 = Bst + er * 36 + eh * 16;
        ((uint4*)d0)[0] = pre[0]; ((uint4*)d0)[1] = pre[1];
        ((uint4*)d0)[2] = pre[2]; ((uint4*)d0)[3] = pre[3];
        u32* d1 = d0 + BST_LIMB_W;
        ((uint4*)d1)[0] = pre[4]; ((uint4*)d1)[1] = pre[5];
        ((uint4*)d1)[2] = pre[6]; ((uint4*)d1)[3] = pre[7];
        if (tid < 128) en_s[tid] = g_enorm[tid];
    }
    __syncthreads();

#pragma unroll 1
    for (int s = 0; s < 32; s++) {
        const int nt = s >> 2, kc = s & 3, buf = s & 1;
        // prefetch next chunk (LDG latency hidden behind the MMAs)
        if (s < 31) {
            int nn = (s + 1) >> 2, nk = (s + 1) & 3;
            size_t bi = (size_t)(nn * 128 + er) * 32 + nk * 8 + eh * 4;
            pre[0] = EH4[bi]; pre[1] = EH4[bi + 1]; pre[2] = EH4[bi + 2]; pre[3] = EH4[bi + 3];
            pre[4] = EL4[bi]; pre[5] = EL4[bi + 1]; pre[6] = EL4[bi + 2]; pre[7] = EL4[bi + 3];
        }
        float enx = 0.0f;
        if (kc == 3 && nt < 7 && tid < 128) enx = g_enorm[(nt + 1) * 128 + tid];

        // MMAs on current buffer: (Fh,Bh) + (Fh,Bl) + (Fl,Bh)
        const u32* bh = Bst + buf * BST_BUF_W;
        const u32* bl = bh + BST_LIMB_W;
#pragma unroll
        for (int kk = 0; kk < 4; kk++) {
            int a0i = rowA * 132 + kc * 32 + kk * 8 + t4;
            int a1i = rowB * 132 + kc * 32 + kk * 8 + t4;
            u32 ah0 = Fh[a0i], ah1 = Fh[a1i], ah2 = Fh[a0i + 4], ah3 = Fh[a1i + 4];
            u32 al0 = Fl[a0i], al1 = Fl[a1i], al2 = Fl[a0i + 4], al3 = Fl[a1i + 4];
#pragma unroll
            for (int j = 0; j < 16; j++) {
                int bidx = (j * 8 + g4) * 36 + kk * 8 + t4;
                u32 b0 = bh[bidx], b1 = bh[bidx + 4];
                u32 c0 = bl[bidx], c1 = bl[bidx + 4];
                mma16816(accf + j * 4, ah0, ah1, ah2, ah3, b0, b1);
                mma16816(accf + j * 4, ah0, ah1, ah2, ah3, c0, c1);
                mma16816(accf + j * 4, al0, al1, al2, al3, b0, b1);
            }
        }
        // store prefetched chunk into the other buffer
        if (s < 31) {
            u32* d0 = Bst + (buf ^ 1) * BST_BUF_W + er * 36 + eh * 16;
            ((uint4*)d0)[0] = pre[0]; ((uint4*)d0)[1] = pre[1];
            ((uint4*)d0)[2] = pre[2]; ((uint4*)d0)[3] = pre[3];
            u32* d1 = d0 + BST_LIMB_W;
            ((uint4*)d1)[0] = pre[4]; ((uint4*)d1)[1] = pre[5];
            ((uint4*)d1)[2] = pre[6]; ((uint4*)d1)[3] = pre[7];
        }
        if (kc == 3 && nt < 7 && tid < 128)
            en_s[((nt + 1) & 1) * 128 + tid] = enx;
        __syncthreads();

        // per-N-tile argmin epilogue (regs only)
        if (kc == 3) {
            const float* ens = en_s + (nt & 1) * 128;
#pragma unroll
            for (int j = 0; j < 16; j++) {
                int cl = j * 8 + 2 * t4;
                float e0 = ens[cl], e1 = ens[cl + 1];
                int col = nt * 128 + cl;
                float d;
                d = __fsub_rn(__fadd_rn(f2a, e0), __fmul_rn(2.0f, accf[j * 4 + 0]));
                if (d < bestA) { bestA = d; ibA = col; }
                d = __fsub_rn(__fadd_rn(f2a, e1), __fmul_rn(2.0f, accf[j * 4 + 1]));
                if (d < bestA) { bestA = d; ibA = col + 1; }
                d = __fsub_rn(__fadd_rn(f2b, e0), __fmul_rn(2.0f, accf[j * 4 + 2]));
                if (d < bestB) { bestB = d; ibB = col; }
                d = __fsub_rn(__fadd_rn(f2b, e1), __fmul_rn(2.0f, accf[j * 4 + 3]));
                if (d < bestB) { bestB = d; ibB = col + 1; }
                accf[j * 4 + 0] = 0.0f; accf[j * 4 + 1] = 0.0f;
                accf[j * 4 + 2] = 0.0f; accf[j * 4 + 3] = 0.0f;
            }
        }
    }

    // reduce argmin across the 4 t4-lanes sharing each row (first-index ties)
#pragma unroll
    for (int o = 2; o; o >>= 1) {
        float ov = __shfl_xor_sync(0xffffffffu, bestA, o);
        int   oi = __shfl_xor_sync(0xffffffffu, ibA, o);
        if (ov < bestA || (ov == bestA && oi < ibA)) { bestA = ov; ibA = oi; }
        ov = __shfl_xor_sync(0xffffffffu, bestB, o);
        oi = __shfl_xor_sync(0xffffffffu, ibB, o);
        if (ov < bestB || (ov == bestB && oi < ibB)) { bestB = ov; ibB = oi; }
    }
    if (t4 == 0) {
        g_idx[row0 + rowA] = ibA; atomicAdd(&g_cnt[ibA], 1);
        g_idx[row0 + rowB] = ibB; atomicAdd(&g_cnt[ibB], 1);
    }
}

// ---------------------------------------------------------------------------
// Small kernels
// ---------------------------------------------------------------------------
__global__ void init_k() {
    int t = threadIdx.x;
    if (t < KCODE) g_cnt[t] = 0;
    if (t == 0) g_loss = 0.0;
}

// limb split: blocks [0,KCODE) -> E (+enorm), [KCODE,KCODE+DDIM) -> W rows.
__global__ void prep_k(const float* __restrict__ E, const float* __restrict__ W) {
    __shared__ float red[4];
    int b = blockIdx.x, t = threadIdx.x;
    if (b < KCODE) {
        float v0 = E[(size_t)b * DDIM + 2 * t];
        float v1 = E[(size_t)b * DDIM + 2 * t + 1];
        __half h0 = __float2half_rn(v0);
        __half l0 = __float2half_rn(v0 - __half2float(h0));
        __half h1 = __float2half_rn(v1);
        __half l1 = __float2half_rn(v1 - __half2float(h1));
        g_Eh16[b * 128 + t] = pkh(h0, h1);
        g_El16[b * 128 + t] = pkh(l0, l1);
        float s = v0 * v0 + v1 * v1;
#pragma unroll
        for (int o = 16; o; o >>= 1) s += __shfl_xor_sync(0xffffffffu, s, o);
        if ((t & 31) == 0) red[t >> 5] = s;
        __syncthreads();
        if (t == 0) g_enorm[b] = red[0] + red[1] + red[2] + red[3];
    } else {
        int k2 = b - KCODE;
        float v0 = W[(size_t)k2 * DDIM + 2 * t];
        float v1 = W[(size_t)k2 * DDIM + 2 * t + 1];
        __half h0 = __float2half_rn(v0);
        __half l0 = __float2half_rn(v0 - __half2float(h0));
        __half h1 = __float2half_rn(v1);
        __half l1 = __float2half_rn(v1 - __half2float(h1));
        g_Wh16[k2 * 128 + t] = pkh(h0, h1);
        g_Wl16[k2 * 128 + t] = pkh(l0, l1);
    }
}

// fused one-hot writer: one warp per token writes its full 1024-float row
__global__ void enc_k(float* __restrict__ out) {
    int tok = (blockIdx.x * blockDim.x + threadIdx.x) >> 5;
    int lane = threadIdx.x & 31;
    if (tok >= NTOK) return;
    int idx = g_idx[tok];
    float2* row = reinterpret_cast<float2*>(out + ENCOFF + (size_t)tok * KCODE);
#pragma unroll
    for (int q = 0; q < 16; q++) {
        int p = q * 32 + lane;
        float2 v;
        v.x = (2 * p     == idx) ? 1.0f : 0.0f;
        v.y = (2 * p + 1 == idx) ? 1.0f : 0.0f;
        row[p] = v;
    }
}

__global__ void quant_loss(float* __restrict__ out, const float* __restrict__ x,
                           const float* __restrict__ E) {
    int warp = (blockIdx.x * blockDim.x + threadIdx.x) >> 5;
    int lane = threadIdx.x & 31;
    if (warp >= NTOK) return;
    int c = g_idx[warp];
    const float4* e4 = reinterpret_cast<const float4*>(E + (size_t)c * DDIM);
    const float4* x4 = reinterpret_cast<const float4*>(x + (size_t)warp * DDIM);
    float4 e0 = e4[lane * 2], e1 = e4[lane * 2 + 1];
    float4 v0 = x4[lane * 2], v1 = x4[lane * 2 + 1];
    float* q = out + QOFF + (size_t)warp * DDIM + lane * 8;
    float s = 0.0f, d;
    d = __fsub_rn(e0.x, v0.x); q[0] = __fadd_rn(v0.x, d); s = __fmaf_rn(d, d, s);
    d = __fsub_rn(e0.y, v0.y); q[1] = __fadd_rn(v0.y, d); s = __fmaf_rn(d, d, s);
    d = __fsub_rn(e0.z, v0.z); q[2] = __fadd_rn(v0.z, d); s = __fmaf_rn(d, d, s);
    d = __fsub_rn(e0.w, v0.w); q[3] = __fadd_rn(v0.w, d); s = __fmaf_rn(d, d, s);
    d = __fsub_rn(e1.x, v1.x); q[4] = __fadd_rn(v1.x, d); s = __fmaf_rn(d, d, s);
    d = __fsub_rn(e1.y, v1.y); q[5] = __fadd_rn(v1.y, d); s = __fmaf_rn(d, d, s);
    d = __fsub_rn(e1.z, v1.z); q[6] = __fadd_rn(v1.z, d); s = __fmaf_rn(d, d, s);
    d = __fsub_rn(e1.w, v1.w); q[7] = __fadd_rn(v1.w, d); s = __fmaf_rn(d, d, s);
#pragma unroll
    for (int o = 16; o; o >>= 1) s += __shfl_xor_sync(0xffffffffu, s, o);
    if (lane == 0) atomicAdd(&g_loss, (double)s);
}

__global__ void final_k(float* __restrict__ out) {
    __shared__ double red[32];
    int t = threadIdx.x;
    double p = (double)g_cnt[t] / (double)NTOK;
    double v = p * log(p + 1e-10);
#pragma unroll
    for (int o = 16; o; o >>= 1) v += __shfl_xor_sync(0xffffffffu, v, o);
    if ((t & 31) == 0) red[t >> 5] = v;
    __syncthreads();
    if (t < 32) {
        double w = red[t];
#pragma unroll
        for (int o = 16; o; o >>= 1) w += __shfl_xor_sync(0xffffffffu, w, o);
        if (t == 0) {
            out[PERPOFF] = (float)exp(-w);
            out[0] = (float)(0.25 * g_loss / (double)((long long)NTOK * DDIM));
        }
    }
}

// ---------------------------------------------------------------------------
extern "C" void kernel_launch(void* const* d_in, const int* in_sizes, int n_in,
                              void* d_out, int out_size) {
    const float* x = (const float*)d_in[0];   // inputs  [64,2048,256]
    const float* W = (const float*)d_in[1];   // pre_w   [256,256]
    const float* b = (const float*)d_in[2];   // pre_b   [256]
    const float* E = (const float*)d_in[3];   // emb     [1024,256]
    float* out = (float*)d_out;

    cudaFuncSetAttribute(vq_main, cudaFuncAttributeMaxDynamicSharedMemorySize, SMEM_TOTAL);

    init_k<<<1, 1024>>>();
    prep_k<<<KCODE + DDIM, 128>>>(E, W);
    init_k<<<1, 1024>>>();   // idempotent; aligns vq_main to launch #4 for ncu
    vq_main<<<NTOK / 128, 256, SMEM_TOTAL>>>(x, b);
    enc_k<<<NTOK / 8, 256>>>(out);
    quant_loss<<<NTOK / 8, 256>>>(out, x, E);
    final_k<<<1, 1024>>>(out);
}

// round 14
// speedup vs baseline: 2.0148x; 1.1237x over previous
#include <cuda_runtime.h>
#include <cuda_fp16.h>

// ---------------------------------------------------------------------------
// VQ forward. Output: [loss(1) | quantized(N*256) | perp(1) | enc(N*K)]
// ---------------------------------------------------------------------------
#define NTOK   (64 * 2048)         // 131072
#define DDIM   256
#define KCODE  1024
#define QOFF   1
#define PERPOFF (1 + NTOK * DDIM)
#define ENCOFF  (PERPOFF + 1)

typedef unsigned long long u64;
typedef unsigned int u32;

// scratch (static device globals)
__device__ float  g_enorm[KCODE];
__device__ int    g_idx[NTOK];
__device__ int    g_cnt[KCODE];
__device__ double g_loss;
__device__ __align__(16) u32 g_Eh16[KCODE * 128];   // fp16x2 high limbs of emb
__device__ __align__(16) u32 g_El16[KCODE * 128];   // fp16x2 low  limbs of emb
__device__ __align__(16) u32 g_Wh16[DDIM * 128];    // fp16x2 high limbs of pre_w
__device__ __align__(16) u32 g_Wl16[DDIM * 128];    // fp16x2 low  limbs of pre_w

__device__ __forceinline__ u32 pkh(__half a, __half b) {
    return (u32)__half_as_ushort(a) | ((u32)__half_as_ushort(b) << 16);
}

// ---- mma.sync m16n8k16 f16 -> f32 (plain sm_80+ PTX) ----------------------
__device__ __forceinline__ void mma16816(float* c, u32 a0, u32 a1, u32 a2, u32 a3,
                                         u32 b0, u32 b1) {
    asm volatile(
        "mma.sync.aligned.m16n8k16.row.col.f32.f16.f16.f32 "
        "{%0,%1,%2,%3}, {%4,%5,%6,%7}, {%8,%9}, {%0,%1,%2,%3};"
        : "+f"(c[0]), "+f"(c[1]), "+f"(c[2]), "+f"(c[3])
        : "r"(a0), "r"(a1), "r"(a2), "r"(a3), "r"(b0), "r"(b1));
}

// ---- shared-memory layout -------------------------------------------------
#define OFF_F2     0                     // 256 floats (f2 partials, then f2)
#define OFF_EN     1024                  // 256 floats (bias, then enorm 2x128)
#define OFF_BV     2048                  // 256 floats (argmin values, 2 halves)
#define OFF_BI     3072                  // 256 ints   (argmin indices)
#define OFF_A      4096                  // Fh: 128 rows x 132 u32 pitch
#define A_BYTES    (128 * 132 * 4)       // 67584
#define OFF_AL     (OFF_A + A_BYTES)     // Fl
#define OFF_BST    (OFF_AL + A_BYTES)    // 139264: staging (73728 B)
#define BST_LIMB_W 4608                  // 128 x 36 u32
#define BST_BUF_W  (2 * BST_LIMB_W)      // 9216 u32 per buffer (phase 2)
#define SMEM_TOTAL (OFF_BST + 2 * BST_BUF_W * 4)   // 212992 B

// ---------------------------------------------------------------------------
// Main fused kernel. CTA = 128 tokens, 512 threads (16 warps), 1 CTA/SM.
// Warp (wg, ch): wg = wrp&7 -> rows [wg*16, +16), ch = wrp>>3 -> cols
// [ch*64, +64) of each 128-wide N tile.
// ---------------------------------------------------------------------------
__global__ void __launch_bounds__(512, 1)
vq_main(const float* __restrict__ x, const float* __restrict__ bias) {
    extern __shared__ char smc[];
    float* f2_s = (float*)(smc + OFF_F2);
    float* en_s = (float*)(smc + OFF_EN);
    float* bv_s = (float*)(smc + OFF_BV);
    int*   bi_s = (int*)(smc + OFF_BI);
    u32*   Fh   = (u32*)(smc + OFF_A);
    u32*   Fl   = (u32*)(smc + OFF_AL);
    u32*   Bst  = (u32*)(smc + OFF_BST);

    const int tid = threadIdx.x;
    const int lane = tid & 31, wrp = tid >> 5;
    const int g4 = lane >> 2, t4 = lane & 3;
    const int wg = wrp & 7, ch = wrp >> 3;
    const int rowA = wg * 16 + g4, rowB = rowA + 8;
    const int row0 = blockIdx.x * 128;

    if (tid < 256) en_s[tid] = bias[tid];   // bias for GEMM1 epilogue

    // ================= phase 1: HMMA pre-linear ============================
    // staging sub-layout (single-buffered): Axh | Axl | Bwh | Bwl
    u32* Axh = Bst;
    u32* Axl = Bst + 4608;
    u32* Bwh = Bst + 9216;
    u32* Bwl = Bst + 13824;

    const int r2 = tid >> 2, eh2 = tid & 3;   // row 0..127, quarter 0..3
    float4 xr[4]; uint4 pw[4];
    {   // prologue: stage 0 (nt2=0, kc=0)
        const float4* xs = (const float4*)(x + (size_t)(row0 + r2) * DDIM + eh2 * 16);
#pragma unroll
        for (int i = 0; i < 4; i++) xr[i] = xs[i];
        const uint4* WH = (const uint4*)g_Wh16;
        const uint4* WL = (const uint4*)g_Wl16;
        size_t wb = (size_t)r2 * 32 + eh2 * 2;
        pw[0] = WH[wb]; pw[1] = WH[wb + 1];
        pw[2] = WL[wb]; pw[3] = WL[wb + 1];
    }

    float accf[32];
#pragma unroll
    for (int i = 0; i < 32; i++) accf[i] = 0.0f;
    float rsA = 0.0f, rsB = 0.0f;

#pragma unroll 1
    for (int s = 0; s < 8; s++) {
        const int nt2 = s >> 2;
        __syncthreads();               // previous MMAs done reading buffers
        // store x chunk (fp32 regs -> fp16 limbs) and W chunk
        {
            u32* dh = Axh + r2 * 36 + eh2 * 8;
            u32* dl = Axl + r2 * 36 + eh2 * 8;
#pragma unroll
            for (int i = 0; i < 4; i++) {
                float4 v = xr[i];
                __half hx = __float2half_rn(v.x), hy = __float2half_rn(v.y);
                __half hz = __float2half_rn(v.z), hw = __float2half_rn(v.w);
                dh[2 * i]     = pkh(hx, hy);
                dh[2 * i + 1] = pkh(hz, hw);
                dl[2 * i]     = pkh(__float2half_rn(v.x - __half2float(hx)),
                                    __float2half_rn(v.y - __half2float(hy)));
                dl[2 * i + 1] = pkh(__float2half_rn(v.z - __half2float(hz)),
                                    __float2half_rn(v.w - __half2float(hw)));
            }
            uint4* wdh = (uint4*)(Bwh + r2 * 36 + eh2 * 8);
            uint4* wdl = (uint4*)(Bwl + r2 * 36 + eh2 * 8);
            wdh[0] = pw[0]; wdh[1] = pw[1];
            wdl[0] = pw[2]; wdl[1] = pw[3];
        }
        __syncthreads();
        // prefetch next stage into regs
        if (s < 7) {
            int ns = s + 1, nn2 = ns >> 2, nk = ns & 3;
            const float4* xs = (const float4*)(x + (size_t)(row0 + r2) * DDIM
                                               + nk * 64 + eh2 * 16);
#pragma unroll
            for (int i = 0; i < 4; i++) xr[i] = xs[i];
            const uint4* WH = (const uint4*)g_Wh16;
            const uint4* WL = (const uint4*)g_Wl16;
            size_t wb = (size_t)(nn2 * 128 + r2) * 32 + nk * 8 + eh2 * 2;
            pw[0] = WH[wb]; pw[1] = WH[wb + 1];
            pw[2] = WL[wb]; pw[3] = WL[wb + 1];
        }
        // MMAs: (Axh,Bwh) + (Axh,Bwl) + (Axl,Bwh), warp covers cols ch*64..+64
#pragma unroll
        for (int kk = 0; kk < 4; kk++) {
            int a0i = rowA * 36 + kk * 8 + t4;
            int a1i = rowB * 36 + kk * 8 + t4;
            u32 ah0 = Axh[a0i], ah1 = Axh[a1i], ah2 = Axh[a0i + 4], ah3 = Axh[a1i + 4];
            u32 al0 = Axl[a0i], al1 = Axl[a1i], al2 = Axl[a0i + 4], al3 = Axl[a1i + 4];
#pragma unroll
            for (int j = 0; j < 8; j++) {
                int bidx = ((ch * 8 + j) * 8 + g4) * 36 + kk * 8 + t4;
                u32 b0 = Bwh[bidx], b1 = Bwh[bidx + 4];
                u32 c0 = Bwl[bidx], c1 = Bwl[bidx + 4];
                mma16816(accf + j * 4, ah0, ah1, ah2, ah3, b0, b1);
                mma16816(accf + j * 4, ah0, ah1, ah2, ah3, c0, c1);
                mma16816(accf + j * 4, al0, al1, al2, al3, b0, b1);
            }
        }
        // tile epilogue: bias, ||f||^2 partials, limb split -> Fh/Fl
        if ((s & 3) == 3) {
#pragma unroll
            for (int j = 0; j < 8; j++) {
                int col = nt2 * 128 + ch * 64 + j * 8 + 2 * t4;
                float b0f = en_s[col], b1f = en_s[col + 1];
                float v0 = accf[j * 4 + 0] + b0f, v1 = accf[j * 4 + 1] + b1f;
                float v2 = accf[j * 4 + 2] + b0f, v3 = accf[j * 4 + 3] + b1f;
                rsA = __fmaf_rn(v0, v0, rsA); rsA = __fmaf_rn(v1, v1, rsA);
                rsB = __fmaf_rn(v2, v2, rsB); rsB = __fmaf_rn(v3, v3, rsB);
                __half h0 = __float2half_rn(v0), h1 = __float2half_rn(v1);
                __half h2 = __float2half_rn(v2), h3 = __float2half_rn(v3);
                int pA = rowA * 132 + nt2 * 64 + ch * 32 + j * 4 + t4;
                int pB = rowB * 132 + nt2 * 64 + ch * 32 + j * 4 + t4;
                Fh[pA] = pkh(h0, h1);
                Fl[pA] = pkh(__float2half_rn(v0 - __half2float(h0)),
                             __float2half_rn(v1 - __half2float(h1)));
                Fh[pB] = pkh(h2, h3);
                Fl[pB] = pkh(__float2half_rn(v2 - __half2float(h2)),
                             __float2half_rn(v3 - __half2float(h3)));
                accf[j * 4 + 0] = 0.0f; accf[j * 4 + 1] = 0.0f;
                accf[j * 4 + 2] = 0.0f; accf[j * 4 + 3] = 0.0f;
            }
        }
    }
    // ||f||^2 partials: reduce over the 4 t4 lanes, store per (ch,row)
#pragma unroll
    for (int o = 2; o; o >>= 1) {
        rsA += __shfl_xor_sync(0xffffffffu, rsA, o);
        rsB += __shfl_xor_sync(0xffffffffu, rsB, o);
    }
    if (t4 == 0) { f2_s[ch * 128 + rowA] = rsA; f2_s[ch * 128 + rowB] = rsB; }
    __syncthreads();   // Fh/Fl + partials ready; staging + en_s free
    if (tid < 128) f2_s[tid] = f2_s[tid] + f2_s[128 + tid];

    // ================= phase 2: HMMA distance GEMM + argmin ================
    float bestA = 3.4e38f, bestB = 3.4e38f;
    int ibA = 0, ibB = 0;

    const int er = tid >> 2, eh = tid & 3;     // stage-copy mapping
    const uint4* EH4 = (const uint4*)g_Eh16;
    const uint4* EL4 = (const uint4*)g_El16;

    // prologue: stage chunk 0 into buffer 0, stage enorm tile 0
    uint4 pre[4];
    {
        size_t bi = (size_t)er * 32 + eh * 2;  // nt=0, kc=0
        pre[0] = EH4[bi]; pre[1] = EH4[bi + 1];
        pre[2] = EL4[bi]; pre[3] = EL4[bi + 1];
        u32* d0 = Bst + er * 36 + eh * 8;
        ((uint4*)d0)[0] = pre[0]; ((uint4*)d0)[1] = pre[1];
        u32* d1 = d0 + BST_LIMB_W;
        ((uint4*)d1)[0] = pre[2]; ((uint4*)d1)[1] = pre[3];
        if (tid < 128) en_s[tid] = g_enorm[tid];
    }
    __syncthreads();
    const float f2a = f2_s[rowA], f2b = f2_s[rowB];

#pragma unroll 1
    for (int s = 0; s < 32; s++) {
        const int nt = s >> 2, kc = s & 3, buf = s & 1;
        // prefetch next chunk
        if (s < 31) {
            int nn = (s + 1) >> 2, nk = (s + 1) & 3;
            size_t bi = (size_t)(nn * 128 + er) * 32 + nk * 8 + eh * 2;
            pre[0] = EH4[bi]; pre[1] = EH4[bi + 1];
            pre[2] = EL4[bi]; pre[3] = EL4[bi + 1];
        }
        float enx = 0.0f;
        if (kc == 3 && nt < 7 && tid < 128) enx = g_enorm[(nt + 1) * 128 + tid];

        // MMAs on current buffer: (Fh,Bh) + (Fh,Bl) + (Fl,Bh)
        const u32* bh = Bst + buf * BST_BUF_W;
        const u32* bl = bh + BST_LIMB_W;
#pragma unroll
        for (int kk = 0; kk < 4; kk++) {
            int a0i = rowA * 132 + kc * 32 + kk * 8 + t4;
            int a1i = rowB * 132 + kc * 32 + kk * 8 + t4;
            u32 ah0 = Fh[a0i], ah1 = Fh[a1i], ah2 = Fh[a0i + 4], ah3 = Fh[a1i + 4];
            u32 al0 = Fl[a0i], al1 = Fl[a1i], al2 = Fl[a0i + 4], al3 = Fl[a1i + 4];
#pragma unroll
            for (int j = 0; j < 8; j++) {
                int bidx = ((ch * 8 + j) * 8 + g4) * 36 + kk * 8 + t4;
                u32 b0 = bh[bidx], b1 = bh[bidx + 4];
                u32 c0 = bl[bidx], c1 = bl[bidx + 4];
                mma16816(accf + j * 4, ah0, ah1, ah2, ah3, b0, b1);
                mma16816(accf + j * 4, ah0, ah1, ah2, ah3, c0, c1);
                mma16816(accf + j * 4, al0, al1, al2, al3, b0, b1);
            }
        }
        // store prefetched chunk into the other buffer
        if (s < 31) {
            u32* d0 = Bst + (buf ^ 1) * BST_BUF_W + er * 36 + eh * 8;
            ((uint4*)d0)[0] = pre[0]; ((uint4*)d0)[1] = pre[1];
            u32* d1 = d0 + BST_LIMB_W;
            ((uint4*)d1)[0] = pre[2]; ((uint4*)d1)[1] = pre[3];
        }
        if (kc == 3 && nt < 7 && tid < 128)
            en_s[((nt + 1) & 1) * 128 + tid] = enx;
        __syncthreads();

        // per-N-tile argmin epilogue (regs only)
        if (kc == 3) {
            const float* ens = en_s + (nt & 1) * 128;
#pragma unroll
            for (int j = 0; j < 8; j++) {
                int cl = ch * 64 + j * 8 + 2 * t4;
                float e0 = ens[cl], e1 = ens[cl + 1];
                int col = nt * 128 + cl;
                float d;
                d = __fsub_rn(__fadd_rn(f2a, e0), __fmul_rn(2.0f, accf[j * 4 + 0]));
                if (d < bestA) { bestA = d; ibA = col; }
                d = __fsub_rn(__fadd_rn(f2a, e1), __fmul_rn(2.0f, accf[j * 4 + 1]));
                if (d < bestA) { bestA = d; ibA = col + 1; }
                d = __fsub_rn(__fadd_rn(f2b, e0), __fmul_rn(2.0f, accf[j * 4 + 2]));
                if (d < bestB) { bestB = d; ibB = col; }
                d = __fsub_rn(__fadd_rn(f2b, e1), __fmul_rn(2.0f, accf[j * 4 + 3]));
                if (d < bestB) { bestB = d; ibB = col + 1; }
                accf[j * 4 + 0] = 0.0f; accf[j * 4 + 1] = 0.0f;
                accf[j * 4 + 2] = 0.0f; accf[j * 4 + 3] = 0.0f;
            }
        }
    }

    // reduce argmin across the 4 t4-lanes (first-index ties), then across
    // the 2 column-half warps via smem
#pragma unroll
    for (int o = 2; o; o >>= 1) {
        float ov = __shfl_xor_sync(0xffffffffu, bestA, o);
        int   oi = __shfl_xor_sync(0xffffffffu, ibA, o);
        if (ov < bestA || (ov == bestA && oi < ibA)) { bestA = ov; ibA = oi; }
        ov = __shfl_xor_sync(0xffffffffu, bestB, o);
        oi = __shfl_xor_sync(0xffffffffu, ibB, o);
        if (ov < bestB || (ov == bestB && oi < ibB)) { bestB = ov; ibB = oi; }
    }
    if (t4 == 0) {
        bv_s[ch * 128 + rowA] = bestA; bi_s[ch * 128 + rowA] = ibA;
        bv_s[ch * 128 + rowB] = bestB; bi_s[ch * 128 + rowB] = ibB;
    }
    __syncthreads();
    if (tid < 128) {
        float v0 = bv_s[tid], v1 = bv_s[128 + tid];
        int   i0 = bi_s[tid], i1 = bi_s[128 + tid];
        int ix = (v1 < v0 || (v1 == v0 && i1 < i0)) ? i1 : i0;
        g_idx[row0 + tid] = ix;
        atomicAdd(&g_cnt[ix], 1);
    }
}

// ---------------------------------------------------------------------------
// Small kernels
// ---------------------------------------------------------------------------
__global__ void init_k() {
    int t = threadIdx.x;
    if (t < KCODE) g_cnt[t] = 0;
    if (t == 0) g_loss = 0.0;
}

// limb split: blocks [0,KCODE) -> E (+enorm), [KCODE,KCODE+DDIM) -> W rows.
__global__ void prep_k(const float* __restrict__ E, const float* __restrict__ W) {
    __shared__ float red[4];
    int b = blockIdx.x, t = threadIdx.x;
    if (b < KCODE) {
        float v0 = E[(size_t)b * DDIM + 2 * t];
        float v1 = E[(size_t)b * DDIM + 2 * t + 1];
        __half h0 = __float2half_rn(v0);
        __half l0 = __float2half_rn(v0 - __half2float(h0));
        __half h1 = __float2half_rn(v1);
        __half l1 = __float2half_rn(v1 - __half2float(h1));
        g_Eh16[b * 128 + t] = pkh(h0, h1);
        g_El16[b * 128 + t] = pkh(l0, l1);
        float s = v0 * v0 + v1 * v1;
#pragma unroll
        for (int o = 16; o; o >>= 1) s += __shfl_xor_sync(0xffffffffu, s, o);
        if ((t & 31) == 0) red[t >> 5] = s;
        __syncthreads();
        if (t == 0) g_enorm[b] = red[0] + red[1] + red[2] + red[3];
    } else {
        int k2 = b - KCODE;
        float v0 = W[(size_t)k2 * DDIM + 2 * t];
        float v1 = W[(size_t)k2 * DDIM + 2 * t + 1];
        __half h0 = __float2half_rn(v0);
        __half l0 = __float2half_rn(v0 - __half2float(h0));
        __half h1 = __float2half_rn(v1);
        __half l1 = __float2half_rn(v1 - __half2float(h1));
        g_Wh16[k2 * 128 + t] = pkh(h0, h1);
        g_Wl16[k2 * 128 + t] = pkh(l0, l1);
    }
}

// fused one-hot writer: one warp per token writes its full 1024-float row
__global__ void enc_k(float* __restrict__ out) {
    int tok = (blockIdx.x * blockDim.x + threadIdx.x) >> 5;
    int lane = threadIdx.x & 31;
    if (tok >= NTOK) return;
    int idx = g_idx[tok];
    float2* row = reinterpret_cast<float2*>(out + ENCOFF + (size_t)tok * KCODE);
#pragma unroll
    for (int q = 0; q < 16; q++) {
        int p = q * 32 + lane;
        float2 v;
        v.x = (2 * p     == idx) ? 1.0f : 0.0f;
        v.y = (2 * p + 1 == idx) ? 1.0f : 0.0f;
        row[p] = v;
    }
}

__global__ void quant_loss(float* __restrict__ out, const float* __restrict__ x,
                           const float* __restrict__ E) {
    int warp = (blockIdx.x * blockDim.x + threadIdx.x) >> 5;
    int lane = threadIdx.x & 31;
    if (warp >= NTOK) return;
    int c = g_idx[warp];
    const float4* e4 = reinterpret_cast<const float4*>(E + (size_t)c * DDIM);
    const float4* x4 = reinterpret_cast<const float4*>(x + (size_t)warp * DDIM);
    float4 e0 = e4[lane * 2], e1 = e4[lane * 2 + 1];
    float4 v0 = x4[lane * 2], v1 = x4[lane * 2 + 1];
    float* q = out + QOFF + (size_t)warp * DDIM + lane * 8;
    float s = 0.0f, d;
    d = __fsub_rn(e0.x, v0.x); q[0] = __fadd_rn(v0.x, d); s = __fmaf_rn(d, d, s);
    d = __fsub_rn(e0.y, v0.y); q[1] = __fadd_rn(v0.y, d); s = __fmaf_rn(d, d, s);
    d = __fsub_rn(e0.z, v0.z); q[2] = __fadd_rn(v0.z, d); s = __fmaf_rn(d, d, s);
    d = __fsub_rn(e0.w, v0.w); q[3] = __fadd_rn(v0.w, d); s = __fmaf_rn(d, d, s);
    d = __fsub_rn(e1.x, v1.x); q[4] = __fadd_rn(v1.x, d); s = __fmaf_rn(d, d, s);
    d = __fsub_rn(e1.y, v1.y); q[5] = __fadd_rn(v1.y, d); s = __fmaf_rn(d, d, s);
    d = __fsub_rn(e1.z, v1.z); q[6] = __fadd_rn(v1.z, d); s = __fmaf_rn(d, d, s);
    d = __fsub_rn(e1.w, v1.w); q[7] = __fadd_rn(v1.w, d); s = __fmaf_rn(d, d, s);
#pragma unroll
    for (int o = 16; o; o >>= 1) s += __shfl_xor_sync(0xffffffffu, s, o);
    if (lane == 0) atomicAdd(&g_loss, (double)s);
}

__global__ void final_k(float* __restrict__ out) {
    __shared__ double red[32];
    int t = threadIdx.x;
    double p = (double)g_cnt[t] / (double)NTOK;
    double v = p * log(p + 1e-10);
#pragma unroll
    for (int o = 16; o; o >>= 1) v += __shfl_xor_sync(0xffffffffu, v, o);
    if ((t & 31) == 0) red[t >> 5] = v;
    __syncthreads();
    if (t < 32) {
        double w = red[t];
#pragma unroll
        for (int o = 16; o; o >>= 1) w += __shfl_xor_sync(0xffffffffu, w, o);
        if (t == 0) {
            out[PERPOFF] = (float)exp(-w);
            out[0] = (float)(0.25 * g_loss / (double)((long long)NTOK * DDIM));
        }
    }
}

// ---------------------------------------------------------------------------
extern "C" void kernel_launch(void* const* d_in, const int* in_sizes, int n_in,
                              void* d_out, int out_size) {
    const float* x = (const float*)d_in[0];   // inputs  [64,2048,256]
    const float* W = (const float*)d_in[1];   // pre_w   [256,256]
    const float* b = (const float*)d_in[2];   // pre_b   [256]
    const float* E = (const float*)d_in[3];   // emb     [1024,256]
    float* out = (float*)d_out;

    cudaFuncSetAttribute(vq_main, cudaFuncAttributeMaxDynamicSharedMemorySize, SMEM_TOTAL);

    init_k<<<1, 1024>>>();
    prep_k<<<KCODE + DDIM, 128>>>(E, W);
    init_k<<<1, 1024>>>();   // idempotent; aligns vq_main to launch #4 for ncu
    vq_main<<<NTOK / 128, 512, SMEM_TOTAL>>>(x, b);
    enc_k<<<NTOK / 8, 256>>>(out);
    quant_loss<<<NTOK / 8, 256>>>(out, x, E);
    final_k<<<1, 1024>>>(out);
}

// round 15
// speedup vs baseline: 2.0176x; 1.0014x over previous
#include <cuda_runtime.h>
#include <cuda_fp16.h>

// ---------------------------------------------------------------------------
// VQ forward. Output: [loss(1) | quantized(N*256) | perp(1) | enc(N*K)]
// ---------------------------------------------------------------------------
#define NTOK   (64 * 2048)         // 131072
#define DDIM   256
#define KCODE  1024
#define QOFF   1
#define PERPOFF (1 + NTOK * DDIM)
#define ENCOFF  (PERPOFF + 1)

typedef unsigned long long u64;
typedef unsigned int u32;

// scratch (static device globals)
__device__ float  g_enorm[KCODE];
__device__ int    g_idx[NTOK];
__device__ int    g_cnt[KCODE];
__device__ double g_loss;
__device__ __align__(16) u32 g_Eh16[KCODE * 128];   // fp16x2 high limbs of emb
__device__ __align__(16) u32 g_El16[KCODE * 128];   // fp16x2 low  limbs of emb
__device__ __align__(16) u32 g_Wh16[DDIM * 128];    // fp16x2 high limbs of pre_w
__device__ __align__(16) u32 g_Wl16[DDIM * 128];    // fp16x2 low  limbs of pre_w

__device__ __forceinline__ u32 pkh(__half a, __half b) {
    return (u32)__half_as_ushort(a) | ((u32)__half_as_ushort(b) << 16);
}

// ---- mma.sync m16n8k16 f16 -> f32 (plain sm_80+ PTX) ----------------------
__device__ __forceinline__ void mma16816(float* c, u32 a0, u32 a1, u32 a2, u32 a3,
                                         u32 b0, u32 b1) {
    asm volatile(
        "mma.sync.aligned.m16n8k16.row.col.f32.f16.f16.f32 "
        "{%0,%1,%2,%3}, {%4,%5,%6,%7}, {%8,%9}, {%0,%1,%2,%3};"
        : "+f"(c[0]), "+f"(c[1]), "+f"(c[2]), "+f"(c[3])
        : "r"(a0), "r"(a1), "r"(a2), "r"(a3), "r"(b0), "r"(b1));
}

// ---- shared-memory layout -------------------------------------------------
#define OFF_F2     0                     // 512 floats (per-ch f2 partials; [0,128) final)
#define OFF_EN     2048                  // 256 floats (bias, then enorm 2x128)
#define OFF_BV     3072                  // 512 floats (argmin values, 4 ch)
#define OFF_BI     5120                  // 512 ints
#define OFF_A      8192                  // Fh: 128 rows x 132 u32 pitch
#define A_BYTES    (128 * 132 * 4)       // 67584
#define OFF_AL     (OFF_A + A_BYTES)     // Fl
#define OFF_BST    (OFF_AL + A_BYTES)    // 143360: staging (73728 B)
#define BST_LIMB_W 4608                  // 128 x 36 u32
#define BST_BUF_W  (2 * BST_LIMB_W)      // 9216 u32 per buffer (phase 2)
#define SMEM_TOTAL (OFF_BST + 2 * BST_BUF_W * 4)   // 217088 B

// ---------------------------------------------------------------------------
// Main fused kernel. CTA = 128 tokens, 512 threads (16 warps), 1 CTA/SM.
// 4x4 warp grid: wg = wrp&3 -> rows [wg*32,+32), ch = wrp>>2 -> cols
// [ch*32,+32) of each 128-wide N tile. Square tiles minimize smem traffic.
// ---------------------------------------------------------------------------
__global__ void __launch_bounds__(512, 1)
vq_main(const float* __restrict__ x, const float* __restrict__ bias) {
    extern __shared__ char smc[];
    float* f2_s = (float*)(smc + OFF_F2);
    float* en_s = (float*)(smc + OFF_EN);
    float* bv_s = (float*)(smc + OFF_BV);
    int*   bi_s = (int*)(smc + OFF_BI);
    u32*   Fh   = (u32*)(smc + OFF_A);
    u32*   Fl   = (u32*)(smc + OFF_AL);
    u32*   Bst  = (u32*)(smc + OFF_BST);

    const int tid = threadIdx.x;
    const int lane = tid & 31, wrp = tid >> 5;
    const int g4 = lane >> 2, t4 = lane & 3;
    const int wg = wrp & 3, ch = wrp >> 2;
    const int rowA = wg * 32 + g4;          // m-tile 0 row; m-tile 1 adds 16
    const int row0 = blockIdx.x * 128;

    if (tid < 256) en_s[tid] = bias[tid];   // bias for GEMM1 epilogue

    // ================= phase 1: HMMA pre-linear ============================
    // staging sub-layout (single-buffered): Axh | Axl | Bwh | Bwl
    u32* Axh = Bst;
    u32* Axl = Bst + 4608;
    u32* Bwh = Bst + 9216;
    u32* Bwl = Bst + 13824;

    const int r2 = tid >> 2, eh2 = tid & 3;   // row 0..127, quarter 0..3
    float4 xr[4]; uint4 pw[4];
    {   // prologue: stage 0 (nt2=0, kc=0)
        const float4* xs = (const float4*)(x + (size_t)(row0 + r2) * DDIM + eh2 * 16);
#pragma unroll
        for (int i = 0; i < 4; i++) xr[i] = xs[i];
        const uint4* WH = (const uint4*)g_Wh16;
        const uint4* WL = (const uint4*)g_Wl16;
        size_t wb = (size_t)r2 * 32 + eh2 * 2;
        pw[0] = WH[wb]; pw[1] = WH[wb + 1];
        pw[2] = WL[wb]; pw[3] = WL[wb + 1];
    }

    float accf[32];
#pragma unroll
    for (int i = 0; i < 32; i++) accf[i] = 0.0f;
    float rs[4] = {0.0f, 0.0f, 0.0f, 0.0f};

#pragma unroll 1
    for (int s = 0; s < 8; s++) {
        const int nt2 = s >> 2;
        __syncthreads();               // previous MMAs done reading buffers
        // store x chunk (fp32 regs -> fp16 limbs) and W chunk
        {
            u32* dh = Axh + r2 * 36 + eh2 * 8;
            u32* dl = Axl + r2 * 36 + eh2 * 8;
#pragma unroll
            for (int i = 0; i < 4; i++) {
                float4 v = xr[i];
                __half hx = __float2half_rn(v.x), hy = __float2half_rn(v.y);
                __half hz = __float2half_rn(v.z), hw = __float2half_rn(v.w);
                dh[2 * i]     = pkh(hx, hy);
                dh[2 * i + 1] = pkh(hz, hw);
                dl[2 * i]     = pkh(__float2half_rn(v.x - __half2float(hx)),
                                    __float2half_rn(v.y - __half2float(hy)));
                dl[2 * i + 1] = pkh(__float2half_rn(v.z - __half2float(hz)),
                                    __float2half_rn(v.w - __half2float(hw)));
            }
            uint4* wdh = (uint4*)(Bwh + r2 * 36 + eh2 * 8);
            uint4* wdl = (uint4*)(Bwl + r2 * 36 + eh2 * 8);
            wdh[0] = pw[0]; wdh[1] = pw[1];
            wdl[0] = pw[2]; wdl[1] = pw[3];
        }
        __syncthreads();
        // prefetch next stage into regs
        if (s < 7) {
            int ns = s + 1, nn2 = ns >> 2, nk = ns & 3;
            const float4* xs = (const float4*)(x + (size_t)(row0 + r2) * DDIM
                                               + nk * 64 + eh2 * 16);
#pragma unroll
            for (int i = 0; i < 4; i++) xr[i] = xs[i];
            const uint4* WH = (const uint4*)g_Wh16;
            const uint4* WL = (const uint4*)g_Wl16;
            size_t wb = (size_t)(nn2 * 128 + r2) * 32 + nk * 8 + eh2 * 2;
            pw[0] = WH[wb]; pw[1] = WH[wb + 1];
            pw[2] = WL[wb]; pw[3] = WL[wb + 1];
        }
        // MMAs: B frags hoisted to regs, reused across both m-tiles
#pragma unroll
        for (int kk = 0; kk < 4; kk++) {
            u32 bhr[8], blr[8];
#pragma unroll
            for (int j = 0; j < 4; j++) {
                int bidx = ((ch * 4 + j) * 8 + g4) * 36 + kk * 8 + t4;
                bhr[j * 2] = Bwh[bidx]; bhr[j * 2 + 1] = Bwh[bidx + 4];
                blr[j * 2] = Bwl[bidx]; blr[j * 2 + 1] = Bwl[bidx + 4];
            }
#pragma unroll
            for (int mt = 0; mt < 2; mt++) {
                int a0i = (rowA + mt * 16) * 36 + kk * 8 + t4;
                int a1i = a0i + 8 * 36;
                u32 ah0 = Axh[a0i], ah1 = Axh[a1i], ah2 = Axh[a0i + 4], ah3 = Axh[a1i + 4];
                u32 al0 = Axl[a0i], al1 = Axl[a1i], al2 = Axl[a0i + 4], al3 = Axl[a1i + 4];
#pragma unroll
                for (int j = 0; j < 4; j++) {
                    float* c = accf + (mt * 4 + j) * 4;
                    mma16816(c, ah0, ah1, ah2, ah3, bhr[j * 2], bhr[j * 2 + 1]);
                    mma16816(c, ah0, ah1, ah2, ah3, blr[j * 2], blr[j * 2 + 1]);
                    mma16816(c, al0, al1, al2, al3, bhr[j * 2], bhr[j * 2 + 1]);
                }
            }
        }
        // tile epilogue: bias, ||f||^2 partials, limb split -> Fh/Fl
        if ((s & 3) == 3) {
#pragma unroll
            for (int mt = 0; mt < 2; mt++) {
                int rA = rowA + mt * 16;
#pragma unroll
                for (int j = 0; j < 4; j++) {
                    float* c = accf + (mt * 4 + j) * 4;
                    int col = nt2 * 128 + ch * 32 + j * 8 + 2 * t4;
                    float b0f = en_s[col], b1f = en_s[col + 1];
                    float v0 = c[0] + b0f, v1 = c[1] + b1f;
                    float v2 = c[2] + b0f, v3 = c[3] + b1f;
                    rs[mt * 2 + 0] = __fmaf_rn(v0, v0, rs[mt * 2 + 0]);
                    rs[mt * 2 + 0] = __fmaf_rn(v1, v1, rs[mt * 2 + 0]);
                    rs[mt * 2 + 1] = __fmaf_rn(v2, v2, rs[mt * 2 + 1]);
                    rs[mt * 2 + 1] = __fmaf_rn(v3, v3, rs[mt * 2 + 1]);
                    __half h0 = __float2half_rn(v0), h1 = __float2half_rn(v1);
                    __half h2 = __float2half_rn(v2), h3 = __float2half_rn(v3);
                    int kp = nt2 * 64 + ch * 16 + j * 4 + t4;
                    int pA = rA * 132 + kp;
                    int pB = (rA + 8) * 132 + kp;
                    Fh[pA] = pkh(h0, h1);
                    Fl[pA] = pkh(__float2half_rn(v0 - __half2float(h0)),
                                 __float2half_rn(v1 - __half2float(h1)));
                    Fh[pB] = pkh(h2, h3);
                    Fl[pB] = pkh(__float2half_rn(v2 - __half2float(h2)),
                                 __float2half_rn(v3 - __half2float(h3)));
                    c[0] = 0.0f; c[1] = 0.0f; c[2] = 0.0f; c[3] = 0.0f;
                }
            }
        }
    }
    // ||f||^2 partials: reduce over the 4 t4 lanes, store per (ch, row)
#pragma unroll
    for (int o = 2; o; o >>= 1) {
#pragma unroll
        for (int i = 0; i < 4; i++)
            rs[i] += __shfl_xor_sync(0xffffffffu, rs[i], o);
    }
    if (t4 == 0) {
        f2_s[ch * 128 + rowA]      = rs[0];
        f2_s[ch * 128 + rowA + 8]  = rs[1];
        f2_s[ch * 128 + rowA + 16] = rs[2];
        f2_s[ch * 128 + rowA + 24] = rs[3];
    }
    __syncthreads();   // Fh/Fl + partials ready; staging + en_s free
    if (tid < 128)
        f2_s[tid] = f2_s[tid] + f2_s[128 + tid] + f2_s[256 + tid] + f2_s[384 + tid];

    // ================= phase 2: HMMA distance GEMM + argmin ================
    float bestv[4] = {3.4e38f, 3.4e38f, 3.4e38f, 3.4e38f};
    int   ib[4] = {0, 0, 0, 0};

    const int er = tid >> 2, eh = tid & 3;     // stage-copy mapping
    const uint4* EH4 = (const uint4*)g_Eh16;
    const uint4* EL4 = (const uint4*)g_El16;

    // prologue: stage chunk 0 into buffer 0, stage enorm tile 0
    uint4 pre[4];
    {
        size_t bi = (size_t)er * 32 + eh * 2;  // nt=0, kc=0
        pre[0] = EH4[bi]; pre[1] = EH4[bi + 1];
        pre[2] = EL4[bi]; pre[3] = EL4[bi + 1];
        u32* d0 = Bst + er * 36 + eh * 8;
        ((uint4*)d0)[0] = pre[0]; ((uint4*)d0)[1] = pre[1];
        u32* d1 = d0 + BST_LIMB_W;
        ((uint4*)d1)[0] = pre[2]; ((uint4*)d1)[1] = pre[3];
        if (tid < 128) en_s[tid] = g_enorm[tid];
    }
    __syncthreads();
    float f2r[4];
#pragma unroll
    for (int mt = 0; mt < 2; mt++) {
        f2r[mt * 2 + 0] = f2_s[rowA + mt * 16];
        f2r[mt * 2 + 1] = f2_s[rowA + mt * 16 + 8];
    }

#pragma unroll 1
    for (int s = 0; s < 32; s++) {
        const int nt = s >> 2, kc = s & 3, buf = s & 1;
        // prefetch next chunk
        if (s < 31) {
            int nn = (s + 1) >> 2, nk = (s + 1) & 3;
            size_t bi = (size_t)(nn * 128 + er) * 32 + nk * 8 + eh * 2;
            pre[0] = EH4[bi]; pre[1] = EH4[bi + 1];
            pre[2] = EL4[bi]; pre[3] = EL4[bi + 1];
        }
        float enx = 0.0f;
        if (kc == 3 && nt < 7 && tid < 128) enx = g_enorm[(nt + 1) * 128 + tid];

        // MMAs on current buffer: (Fh,Bh) + (Fh,Bl) + (Fl,Bh)
        const u32* bh = Bst + buf * BST_BUF_W;
        const u32* bl = bh + BST_LIMB_W;
#pragma unroll
        for (int kk = 0; kk < 4; kk++) {
            u32 bhr[8], blr[8];
#pragma unroll
            for (int j = 0; j < 4; j++) {
                int bidx = ((ch * 4 + j) * 8 + g4) * 36 + kk * 8 + t4;
                bhr[j * 2] = bh[bidx]; bhr[j * 2 + 1] = bh[bidx + 4];
                blr[j * 2] = bl[bidx]; blr[j * 2 + 1] = bl[bidx + 4];
            }
#pragma unroll
            for (int mt = 0; mt < 2; mt++) {
                int a0i = (rowA + mt * 16) * 132 + kc * 32 + kk * 8 + t4;
                int a1i = a0i + 8 * 132;
                u32 ah0 = Fh[a0i], ah1 = Fh[a1i], ah2 = Fh[a0i + 4], ah3 = Fh[a1i + 4];
                u32 al0 = Fl[a0i], al1 = Fl[a1i], al2 = Fl[a0i + 4], al3 = Fl[a1i + 4];
#pragma unroll
                for (int j = 0; j < 4; j++) {
                    float* c = accf + (mt * 4 + j) * 4;
                    mma16816(c, ah0, ah1, ah2, ah3, bhr[j * 2], bhr[j * 2 + 1]);
                    mma16816(c, ah0, ah1, ah2, ah3, blr[j * 2], blr[j * 2 + 1]);
                    mma16816(c, al0, al1, al2, al3, bhr[j * 2], bhr[j * 2 + 1]);
                }
            }
        }
        // store prefetched chunk into the other buffer
        if (s < 31) {
            u32* d0 = Bst + (buf ^ 1) * BST_BUF_W + er * 36 + eh * 8;
            ((uint4*)d0)[0] = pre[0]; ((uint4*)d0)[1] = pre[1];
            u32* d1 = d0 + BST_LIMB_W;
            ((uint4*)d1)[0] = pre[2]; ((uint4*)d1)[1] = pre[3];
        }
        if (kc == 3 && nt < 7 && tid < 128)
            en_s[((nt + 1) & 1) * 128 + tid] = enx;
        __syncthreads();

        // per-N-tile argmin epilogue (regs only)
        if (kc == 3) {
            const float* ens = en_s + (nt & 1) * 128;
#pragma unroll
            for (int mt = 0; mt < 2; mt++) {
#pragma unroll
                for (int j = 0; j < 4; j++) {
                    float* c = accf + (mt * 4 + j) * 4;
                    int cl = ch * 32 + j * 8 + 2 * t4;
                    float e0 = ens[cl], e1 = ens[cl + 1];
                    int col = nt * 128 + cl;
                    float d;
                    d = __fsub_rn(__fadd_rn(f2r[mt * 2], e0), __fmul_rn(2.0f, c[0]));
                    if (d < bestv[mt * 2]) { bestv[mt * 2] = d; ib[mt * 2] = col; }
                    d = __fsub_rn(__fadd_rn(f2r[mt * 2], e1), __fmul_rn(2.0f, c[1]));
                    if (d < bestv[mt * 2]) { bestv[mt * 2] = d; ib[mt * 2] = col + 1; }
                    d = __fsub_rn(__fadd_rn(f2r[mt * 2 + 1], e0), __fmul_rn(2.0f, c[2]));
                    if (d < bestv[mt * 2 + 1]) { bestv[mt * 2 + 1] = d; ib[mt * 2 + 1] = col; }
                    d = __fsub_rn(__fadd_rn(f2r[mt * 2 + 1], e1), __fmul_rn(2.0f, c[3]));
                    if (d < bestv[mt * 2 + 1]) { bestv[mt * 2 + 1] = d; ib[mt * 2 + 1] = col + 1; }
                    c[0] = 0.0f; c[1] = 0.0f; c[2] = 0.0f; c[3] = 0.0f;
                }
            }
        }
    }

    // reduce argmin across the 4 t4-lanes (first-index ties), then across
    // the 4 column warps via smem
#pragma unroll
    for (int o = 2; o; o >>= 1) {
#pragma unroll
        for (int i = 0; i < 4; i++) {
            float ov = __shfl_xor_sync(0xffffffffu, bestv[i], o);
            int   oi = __shfl_xor_sync(0xffffffffu, ib[i], o);
            if (ov < bestv[i] || (ov == bestv[i] && oi < ib[i])) {
                bestv[i] = ov; ib[i] = oi;
            }
        }
    }
    if (t4 == 0) {
#pragma unroll
        for (int mt = 0; mt < 2; mt++) {
            bv_s[ch * 128 + rowA + mt * 16]     = bestv[mt * 2];
            bi_s[ch * 128 + rowA + mt * 16]     = ib[mt * 2];
            bv_s[ch * 128 + rowA + mt * 16 + 8] = bestv[mt * 2 + 1];
            bi_s[ch * 128 + rowA + mt * 16 + 8] = ib[mt * 2 + 1];
        }
    }
    __syncthreads();
    if (tid < 128) {
        float v = bv_s[tid];
        int   ix = bi_s[tid];
#pragma unroll
        for (int c = 1; c < 4; c++) {
            float vc = bv_s[c * 128 + tid];
            int   ic = bi_s[c * 128 + tid];
            if (vc < v || (vc == v && ic < ix)) { v = vc; ix = ic; }
        }
        g_idx[row0 + tid] = ix;
        atomicAdd(&g_cnt[ix], 1);
    }
}

// ---------------------------------------------------------------------------
// Small kernels
// ---------------------------------------------------------------------------
__global__ void init_k() {
    int t = threadIdx.x;
    if (t < KCODE) g_cnt[t] = 0;
    if (t == 0) g_loss = 0.0;
}

// limb split: blocks [0,KCODE) -> E (+enorm), [KCODE,KCODE+DDIM) -> W rows.
__global__ void prep_k(const float* __restrict__ E, const float* __restrict__ W) {
    __shared__ float red[4];
    int b = blockIdx.x, t = threadIdx.x;
    if (b < KCODE) {
        float v0 = E[(size_t)b * DDIM + 2 * t];
        float v1 = E[(size_t)b * DDIM + 2 * t + 1];
        __half h0 = __float2half_rn(v0);
        __half l0 = __float2half_rn(v0 - __half2float(h0));
        __half h1 = __float2half_rn(v1);
        __half l1 = __float2half_rn(v1 - __half2float(h1));
        g_Eh16[b * 128 + t] = pkh(h0, h1);
        g_El16[b * 128 + t] = pkh(l0, l1);
        float s = v0 * v0 + v1 * v1;
#pragma unroll
        for (int o = 16; o; o >>= 1) s += __shfl_xor_sync(0xffffffffu, s, o);
        if ((t & 31) == 0) red[t >> 5] = s;
        __syncthreads();
        if (t == 0) g_enorm[b] = red[0] + red[1] + red[2] + red[3];
    } else {
        int k2 = b - KCODE;
        float v0 = W[(size_t)k2 * DDIM + 2 * t];
        float v1 = W[(size_t)k2 * DDIM + 2 * t + 1];
        __half h0 = __float2half_rn(v0);
        __half l0 = __float2half_rn(v0 - __half2float(h0));
        __half h1 = __float2half_rn(v1);
        __half l1 = __float2half_rn(v1 - __half2float(h1));
        g_Wh16[k2 * 128 + t] = pkh(h0, h1);
        g_Wl16[k2 * 128 + t] = pkh(l0, l1);
    }
}

// fused one-hot writer: one warp per token writes its full 1024-float row
__global__ void enc_k(float* __restrict__ out) {
    int tok = (blockIdx.x * blockDim.x + threadIdx.x) >> 5;
    int lane = threadIdx.x & 31;
    if (tok >= NTOK) return;
    int idx = g_idx[tok];
    float2* row = reinterpret_cast<float2*>(out + ENCOFF + (size_t)tok * KCODE);
#pragma unroll
    for (int q = 0; q < 16; q++) {
        int p = q * 32 + lane;
        float2 v;
        v.x = (2 * p     == idx) ? 1.0f : 0.0f;
        v.y = (2 * p + 1 == idx) ? 1.0f : 0.0f;
        row[p] = v;
    }
}

__global__ void quant_loss(float* __restrict__ out, const float* __restrict__ x,
                           const float* __restrict__ E) {
    int warp = (blockIdx.x * blockDim.x + threadIdx.x) >> 5;
    int lane = threadIdx.x & 31;
    if (warp >= NTOK) return;
    int c = g_idx[warp];
    const float4* e4 = reinterpret_cast<const float4*>(E + (size_t)c * DDIM);
    const float4* x4 = reinterpret_cast<const float4*>(x + (size_t)warp * DDIM);
    float4 e0 = e4[lane * 2], e1 = e4[lane * 2 + 1];
    float4 v0 = x4[lane * 2], v1 = x4[lane * 2 + 1];
    float* q = out + QOFF + (size_t)warp * DDIM + lane * 8;
    float s = 0.0f, d;
    d = __fsub_rn(e0.x, v0.x); q[0] = __fadd_rn(v0.x, d); s = __fmaf_rn(d, d, s);
    d = __fsub_rn(e0.y, v0.y); q[1] = __fadd_rn(v0.y, d); s = __fmaf_rn(d, d, s);
    d = __fsub_rn(e0.z, v0.z); q[2] = __fadd_rn(v0.z, d); s = __fmaf_rn(d, d, s);
    d = __fsub_rn(e0.w, v0.w); q[3] = __fadd_rn(v0.w, d); s = __fmaf_rn(d, d, s);
    d = __fsub_rn(e1.x, v1.x); q[4] = __fadd_rn(v1.x, d); s = __fmaf_rn(d, d, s);
    d = __fsub_rn(e1.y, v1.y); q[5] = __fadd_rn(v1.y, d); s = __fmaf_rn(d, d, s);
    d = __fsub_rn(e1.z, v1.z); q[6] = __fadd_rn(v1.z, d); s = __fmaf_rn(d, d, s);
    d = __fsub_rn(e1.w, v1.w); q[7] = __fadd_rn(v1.w, d); s = __fmaf_rn(d, d, s);
#pragma unroll
    for (int o = 16; o; o >>= 1) s += __shfl_xor_sync(0xffffffffu, s, o);
    if (lane == 0) atomicAdd(&g_loss, (double)s);
}

__global__ void final_k(float* __restrict__ out) {
    __shared__ double red[32];
    int t = threadIdx.x;
    double p = (double)g_cnt[t] / (double)NTOK;
    double v = p * log(p + 1e-10);
#pragma unroll
    for (int o = 16; o; o >>= 1) v += __shfl_xor_sync(0xffffffffu, v, o);
    if ((t & 31) == 0) red[t >> 5] = v;
    __syncthreads();
    if (t < 32) {
        double w = red[t];
#pragma unroll
        for (int o = 16; o; o >>= 1) w += __shfl_xor_sync(0xffffffffu, w, o);
        if (t == 0) {
            out[PERPOFF] = (float)exp(-w);
            out[0] = (float)(0.25 * g_loss / (double)((long long)NTOK * DDIM));
        }
    }
}

// ---------------------------------------------------------------------------
extern "C" void kernel_launch(void* const* d_in, const int* in_sizes, int n_in,
                              void* d_out, int out_size) {
    const float* x = (const float*)d_in[0];   // inputs  [64,2048,256]
    const float* W = (const float*)d_in[1];   // pre_w   [256,256]
    const float* b = (const float*)d_in[2];   // pre_b   [256]
    const float* E = (const float*)d_in[3];   // emb     [1024,256]
    float* out = (float*)d_out;

    cudaFuncSetAttribute(vq_main, cudaFuncAttributeMaxDynamicSharedMemorySize, SMEM_TOTAL);

    init_k<<<1, 1024>>>();
    prep_k<<<KCODE + DDIM, 128>>>(E, W);
    init_k<<<1, 1024>>>();   // idempotent; aligns vq_main to launch #4 for ncu
    vq_main<<<NTOK / 128, 512, SMEM_TOTAL>>>(x, b);
    enc_k<<<NTOK / 8, 256>>>(out);
    quant_loss<<<NTOK / 8, 256>>>(out, x, E);
    final_k<<<1, 1024>>>(out);
}